// round 1
// baseline (speedup 1.0000x reference)
#include <cuda_runtime.h>
#include <cstdint>

#define NN 20000      // nodes
#define KNB 32        // neighbors per node
#define DD 128        // feature dim (in == out)
#define GT 4096       // gate table resolution over [0, 64]

// ---------------- scratch (device globals; no runtime allocation) -----------
__device__ float g_gate_table[GT + 1];
__device__ float g_hself[NN * DD];     // h_self = x_self @ W + b   (10.24 MB)
__device__ float g_sself[NN];          // s_self = h_self . phi_s

// ---------------- helpers ---------------------------------------------------
__device__ __forceinline__ float f_tf32(float x) {
    uint32_t u;
    asm("cvt.rna.tf32.f32 %0, %1;" : "=r"(u) : "f"(x));
    return __uint_as_float(u);
}
__device__ __forceinline__ uint32_t fbits(float x) { return __float_as_uint(x); }

__device__ __forceinline__ void mma8(float* c, const uint32_t* a, const uint32_t* b) {
    asm volatile(
        "mma.sync.aligned.m16n8k8.row.col.f32.tf32.tf32.f32 "
        "{%0,%1,%2,%3}, {%4,%5,%6,%7}, {%8,%9}, {%0,%1,%2,%3};\n"
        : "+f"(c[0]), "+f"(c[1]), "+f"(c[2]), "+f"(c[3])
        : "r"(a[0]), "r"(a[1]), "r"(a[2]), "r"(a[3]), "r"(b[0]), "r"(b[1]));
}

// Shared memory layout (floats)
#define AS_F (128 * 36)       // A chunk 128 rows x 32 k, pad->36 (conflict-free frags)
#define WS_F (32 * 136)       // W chunk 32 k x 128 n, pad->136 (conflict-free frags)
#define HS_F (128 * 132)      // result tile 128 x 128, pad->132
#define SMEM_FLOATS (AS_F + WS_F + HS_F + 128 * 5 + 8)

// 128x128x128 GEMM tile: C = A[128,128] @ W[128,128], tf32 MMA, K-chunked by 32.
// 256 threads = 8 warps laid out 4(M) x 2(N); each warp: 32x64 via 2x8 m16n8 tiles.
__device__ __forceinline__ void gemm_tile(
    const float* __restrict__ Abase, int valid_rows,
    const float* __restrict__ W,
    float* As, float* Wsh,
    float (&acc)[2][8][4])
{
    const int t = threadIdx.x;
    const int lane = t & 31, wid = t >> 5;
    const int wm = wid & 3, wn = wid >> 2;

    #pragma unroll
    for (int kc = 0; kc < 4; kc++) {
        // ---- load A chunk: 128 x 32  (1024 float4 across 256 threads) ----
        int e = t;
        #pragma unroll
        for (int it = 0; it < 4; it++, e += 256) {
            int row = e >> 3;
            int c4 = (e & 7) << 2;
            float4 v = make_float4(0.f, 0.f, 0.f, 0.f);
            if (row < valid_rows)
                v = *(const float4*)(Abase + row * DD + kc * 32 + c4);
            v.x = f_tf32(v.x); v.y = f_tf32(v.y); v.z = f_tf32(v.z); v.w = f_tf32(v.w);
            *(float4*)(As + row * 36 + c4) = v;
        }
        // ---- load W chunk: 32 x 128 ----
        e = t;
        #pragma unroll
        for (int it = 0; it < 4; it++, e += 256) {
            int row = e >> 5;
            int c4 = (e & 31) << 2;
            float4 v = *(const float4*)(W + (kc * 32 + row) * DD + c4);
            v.x = f_tf32(v.x); v.y = f_tf32(v.y); v.z = f_tf32(v.z); v.w = f_tf32(v.w);
            *(float4*)(Wsh + row * 136 + c4) = v;
        }
        __syncthreads();

        #pragma unroll
        for (int ks = 0; ks < 4; ks++) {
            const int kk = ks * 8;
            uint32_t a[2][4];
            const int r0 = wm * 32 + (lane >> 2);
            const int ca = kk + (lane & 3);
            a[0][0] = fbits(As[(r0     ) * 36 + ca]);
            a[0][1] = fbits(As[(r0 +  8) * 36 + ca]);
            a[0][2] = fbits(As[(r0     ) * 36 + ca + 4]);
            a[0][3] = fbits(As[(r0 +  8) * 36 + ca + 4]);
            a[1][0] = fbits(As[(r0 + 16) * 36 + ca]);
            a[1][1] = fbits(As[(r0 + 24) * 36 + ca]);
            a[1][2] = fbits(As[(r0 + 16) * 36 + ca + 4]);
            a[1][3] = fbits(As[(r0 + 24) * 36 + ca + 4]);
            #pragma unroll
            for (int nt = 0; nt < 8; nt++) {
                const int nc = wn * 64 + nt * 8 + (lane >> 2);
                uint32_t b[2];
                b[0] = fbits(Wsh[(kk + (lane & 3)    ) * 136 + nc]);
                b[1] = fbits(Wsh[(kk + (lane & 3) + 4) * 136 + nc]);
                mma8(acc[0][nt], a[0], b);
                mma8(acc[1][nt], a[1], b);
            }
        }
        __syncthreads();
    }
}

// Store accumulators (+bias) into Hs[128][132]
__device__ __forceinline__ void store_hs(float (&acc)[2][8][4], float* Hs,
                                         const float* bias_s)
{
    const int t = threadIdx.x;
    const int lane = t & 31, wid = t >> 5;
    const int wm = wid & 3, wn = wid >> 2;
    const int r0 = wm * 32 + (lane >> 2);
    #pragma unroll
    for (int mt = 0; mt < 2; mt++) {
        #pragma unroll
        for (int nt = 0; nt < 8; nt++) {
            const int r = r0 + mt * 16;
            const int c = wn * 64 + nt * 8 + (lane & 3) * 2;
            float2 v0 = make_float2(acc[mt][nt][0] + bias_s[c],
                                    acc[mt][nt][1] + bias_s[c + 1]);
            float2 v1 = make_float2(acc[mt][nt][2] + bias_s[c],
                                    acc[mt][nt][3] + bias_s[c + 1]);
            *(float2*)(Hs + r * 132 + c) = v0;
            *(float2*)(Hs + (r + 8) * 132 + c) = v1;
        }
    }
}

// ---------------- gate lookup table ----------------------------------------
__global__ void gate_table_kernel(const float* __restrict__ w1, const float* __restrict__ b1,
                                  const float* __restrict__ w2, const float* __restrict__ b2)
{
    int i = blockIdx.x * blockDim.x + threadIdx.x;
    if (i <= GT) {
        float d = (float)i * (64.0f / (float)GT);
        float z = b2[0];
        float bb = b1[0];
        #pragma unroll
        for (int g = 0; g < 32; g++) {
            float x = d * w1[g] + bb;
            float s = 1.0f / (1.0f + __expf(-x));
            z += s * w2[g];
        }
        g_gate_table[i] = 1.0f / (1.0f + __expf(-z));
    }
}

// ---------------- kernel A: h_self + s_self ---------------------------------
__global__ void __launch_bounds__(256, 2) hself_kernel(
    const float* __restrict__ x_self, const float* __restrict__ W,
    const float* __restrict__ bias, const float* __restrict__ phi)
{
    extern __shared__ float sm[];
    float* As = sm;
    float* Wsh = As + AS_F;
    float* Hs = Wsh + WS_F;
    float* bias_s = Hs + HS_F;
    float* ps = bias_s + 128;

    const int t = threadIdx.x;
    if (t < 128) { bias_s[t] = bias[t]; ps[t] = phi[128 + t]; }

    const int row_base = blockIdx.x * 128;
    int valid = NN - row_base;
    if (valid > 128) valid = 128;

    float acc[2][8][4] = {};
    gemm_tile(x_self + (size_t)row_base * DD, valid, W, As, Wsh, acc);
    store_hs(acc, Hs, bias_s);
    __syncthreads();

    // write h_self to scratch
    {
        const int r = t >> 1;
        const int c0 = (t & 1) * 64;
        if (r < valid) {
            float* dst = g_hself + (size_t)(row_base + r) * DD + c0;
            const float* src = Hs + r * 132 + c0;
            #pragma unroll
            for (int j = 0; j < 16; j++)
                ((float4*)dst)[j] = ((const float4*)src)[j];
        }
    }
    // s_self = h_self . phi_s (warp per 16 rows)
    {
        const int lane = t & 31, wid = t >> 5;
        #pragma unroll
        for (int i = 0; i < 16; i++) {
            const int r = wid * 16 + i;
            float p = 0.f;
            #pragma unroll
            for (int j = 0; j < 4; j++)
                p += Hs[r * 132 + lane + 32 * j] * ps[lane + 32 * j];
            #pragma unroll
            for (int off = 16; off; off >>= 1)
                p += __shfl_xor_sync(0xffffffffu, p, off);
            if (lane == 0 && r < valid) g_sself[row_base + r] = p;
        }
    }
}

// ---------------- kernel B: fused neighbor GEMM + attention -----------------
__global__ void __launch_bounds__(256, 2) fused_kernel(
    const float* __restrict__ x_nb, const float* __restrict__ W,
    const float* __restrict__ bias, const float* __restrict__ phi,
    const float* __restrict__ deg,
    const float* __restrict__ wsp, const float* __restrict__ wnp,
    float* __restrict__ out)
{
    extern __shared__ float sm[];
    float* As = sm;
    float* Wsh = As + AS_F;
    float* Hs = Wsh + WS_F;
    float* bias_s = Hs + HS_F;
    float* pn = bias_s + 128;
    float* gate_s = pn + 128;
    float* score_s = gate_s + 128;
    float* attg = score_s + 128;
    float* sself = attg + 128;

    const int t = threadIdx.x;
    const int node0 = blockIdx.x * 4;

    if (t < 128) {
        bias_s[t] = bias[t];
        pn[t] = phi[t];
        // gate via table lookup + lerp
        float d = deg[(size_t)node0 * KNB + t];
        float u = d * ((float)GT / 64.0f);
        u = fminf(fmaxf(u, 0.0f), (float)GT - 0.001f);
        int i = (int)u;
        float f = u - (float)i;
        float g0 = g_gate_table[i];
        gate_s[t] = g0 + (g_gate_table[i + 1] - g0) * f;
    }
    if (t < 4) sself[t] = g_sself[node0 + t];

    float acc[2][8][4] = {};
    gemm_tile(x_nb + (size_t)node0 * KNB * DD, 128, W, As, Wsh, acc);
    store_hs(acc, Hs, bias_s);
    __syncthreads();

    // scores: leaky_relu(h_nb . phi_n + s_self), warp per 16 rows
    {
        const int lane = t & 31, wid = t >> 5;
        #pragma unroll
        for (int i = 0; i < 16; i++) {
            const int r = wid * 16 + i;
            float p = 0.f;
            #pragma unroll
            for (int j = 0; j < 4; j++)
                p += Hs[r * 132 + lane + 32 * j] * pn[lane + 32 * j];
            #pragma unroll
            for (int off = 16; off; off >>= 1)
                p += __shfl_xor_sync(0xffffffffu, p, off);
            if (lane == 0) {
                float sc = p + sself[r >> 5];
                score_s[r] = (sc > 0.f) ? sc : 0.2f * sc;
            }
        }
    }
    __syncthreads();

    // softmax over 32 neighbors, fold in gate (warps 0..3 handle node 0..3)
    {
        const int lane = t & 31, wid = t >> 5;
        if (wid < 4) {
            float s = score_s[wid * 32 + lane];
            float m = s;
            #pragma unroll
            for (int off = 16; off; off >>= 1)
                m = fmaxf(m, __shfl_xor_sync(0xffffffffu, m, off));
            float e = __expf(s - m);
            float ssum = e;
            #pragma unroll
            for (int off = 16; off; off >>= 1)
                ssum += __shfl_xor_sync(0xffffffffu, ssum, off);
            attg[wid * 32 + lane] = (e / ssum) * gate_s[wid * 32 + lane];
        }
    }
    __syncthreads();

    // neighbor_info + final relu(ws*h_self + wn*ni)
    {
        const float wsv = wsp[0], wnv = wnp[0];
        const int node = t >> 6;
        const int c = (t & 63) << 1;
        float a0 = 0.f, a1 = 0.f;
        #pragma unroll
        for (int k = 0; k < 32; k++) {
            float w = attg[node * 32 + k];
            float2 h = *(const float2*)(Hs + (node * 32 + k) * 132 + c);
            a0 = fmaf(w, h.x, a0);
            a1 = fmaf(w, h.y, a1);
        }
        const size_t gr = (size_t)(node0 + node) * DD + c;
        float2 hsv = *(const float2*)(g_hself + gr);
        float o0 = wsv * hsv.x + wnv * a0;
        float o1 = wsv * hsv.y + wnv * a1;
        o0 = (o0 > 0.f) ? o0 : 0.f;
        o1 = (o1 > 0.f) ? o1 : 0.f;
        *(float2*)(out + gr) = make_float2(o0, o1);
    }
}

// ---------------- launch -----------------------------------------------------
extern "C" void kernel_launch(void* const* d_in, const int* in_sizes, int n_in,
                              void* d_out, int out_size)
{
    const float* x_self = (const float*)d_in[0];
    const float* x_nb   = (const float*)d_in[1];
    const float* deg    = (const float*)d_in[2];
    const float* W      = (const float*)d_in[3];
    const float* bias   = (const float*)d_in[4];
    const float* phi    = (const float*)d_in[5];
    const float* w1     = (const float*)d_in[6];
    const float* b1     = (const float*)d_in[7];
    const float* w2     = (const float*)d_in[8];
    const float* b2     = (const float*)d_in[9];
    const float* wsp    = (const float*)d_in[10];
    const float* wnp    = (const float*)d_in[11];
    float* out = (float*)d_out;

    constexpr size_t SMEM = SMEM_FLOATS * sizeof(float);
    cudaFuncSetAttribute(hself_kernel, cudaFuncAttributeMaxDynamicSharedMemorySize, (int)SMEM);
    cudaFuncSetAttribute(fused_kernel, cudaFuncAttributeMaxDynamicSharedMemorySize, (int)SMEM);

    gate_table_kernel<<<(GT + 1 + 255) / 256, 256>>>(w1, b1, w2, b2);
    hself_kernel<<<(NN + 127) / 128, 256, SMEM>>>(x_self, W, bias, phi);
    fused_kernel<<<NN / 4, 256, SMEM>>>(x_nb, W, bias, phi, deg, wsp, wnp, out);
}

// round 2
// speedup vs baseline: 1.7758x; 1.7758x over previous
#include <cuda_runtime.h>
#include <cstdint>

#define NN 20000
#define KNB 32
#define DD 128
#define GT 4096

// ---------------- device scratch (no runtime allocation) --------------------
__device__ float g_gate_table[GT + 1];
__device__ float g_Wt[DD * DD];      // tf32-converted weights (k-major [k][n])
__device__ float g_hself[NN * DD];   // h_self = x_self @ W + b
__device__ float g_sself[NN];        // s_self = h_self . phi_s
__device__ float g_Kbn;              // bias . phi_n

// ---------------- helpers ---------------------------------------------------
__device__ __forceinline__ float f_tf32(float x) {
    uint32_t u; asm("cvt.rna.tf32.f32 %0, %1;" : "=r"(u) : "f"(x));
    return __uint_as_float(u);
}
__device__ __forceinline__ uint32_t fbits(float x) { return __float_as_uint(x); }
__device__ __forceinline__ uint32_t s2u(const void* p) {
    return (uint32_t)__cvta_generic_to_shared(p);
}
__device__ __forceinline__ void mma8(float* c, const uint32_t* a, const uint32_t* b) {
    asm volatile(
        "mma.sync.aligned.m16n8k8.row.col.f32.tf32.tf32.f32 "
        "{%0,%1,%2,%3}, {%4,%5,%6,%7}, {%8,%9}, {%0,%1,%2,%3};\n"
        : "+f"(c[0]), "+f"(c[1]), "+f"(c[2]), "+f"(c[3])
        : "r"(a[0]), "r"(a[1]), "r"(a[2]), "r"(a[3]), "r"(b[0]), "r"(b[1]));
}
__device__ __forceinline__ void cp16(uint32_t sa, const float* g, bool v) {
    int sz = v ? 16 : 0;
    asm volatile("cp.async.cg.shared.global [%0], [%1], 16, %2;\n"
                 :: "r"(sa), "l"(g), "r"(sz));
}
#define CP_COMMIT() asm volatile("cp.async.commit_group;\n" ::: "memory")

// ---------------- shared memory layout (float offsets) ----------------------
#define OFF_A     0        // 2 stages x 128x32
#define OFF_W     8192     // 2 stages x 32x128
#define OFF_PN    16384    // phi (128)
#define OFF_BIAS  16512    // bias (128)
#define OFF_GATE  16640    // gate (128)
#define OFF_SCORE 16768    // score accum (128)
#define OFF_ATT   16896    // att*gate (128)
#define OFF_NI    17024    // ni tile 4x128
#define OFF_GS    17536    // gate-weighted att sums (4)
#define SMEM_FLOATS 17544
#define SMEM_BYTES (SMEM_FLOATS * 4)

// ---------------- pipeline stages -------------------------------------------
// A chunk: 128 rows x 32 cols, swizzle col4 ^= (row&7)<<2
__device__ __forceinline__ void stageA(float* sm, int buf, const float* Ag, int valid) {
    const int t = threadIdx.x;
    float* base = sm + OFF_A + buf * 4096;
    #pragma unroll
    for (int i = 0; i < 4; i++) {
        int e = t + i * 256;
        int row = e >> 3, c4 = (e & 7) << 2;
        uint32_t sa = s2u(base + row * 32 + (c4 ^ ((row & 7) << 2)));
        cp16(sa, Ag + row * DD + c4, row < valid);
    }
}
// W chunk: 32 rows(k) x 128 cols(n), swizzle col4 ^= (k&3)<<3
__device__ __forceinline__ void stageW(float* sm, int buf, const float* Wg) {
    const int t = threadIdx.x;
    float* base = sm + OFF_W + buf * 4096;
    #pragma unroll
    for (int i = 0; i < 4; i++) {
        int e = t + i * 256;
        int row = e >> 5, c4 = (e & 31) << 2;
        uint32_t sa = s2u(base + row * 128 + (c4 ^ ((row & 3) << 3)));
        cp16(sa, Wg + row * DD + c4, true);
    }
}

// compute one 32-K chunk into acc
__device__ __forceinline__ void compute_chunk(
    const float* As, const float* Ws, float (&acc)[2][8][4],
    int wm, int wn, int la, int lr)
{
    #pragma unroll
    for (int ks = 0; ks < 4; ks++) {
        const int kk = ks * 8;
        const int ca = (kk + la) ^ (lr << 2);
        const int ca2 = ca ^ 4;
        const int rb = (wm * 32 + lr) * 32;
        uint32_t a0[4], a1[4];
        a0[0] = fbits(f_tf32(As[rb + ca]));
        a0[1] = fbits(f_tf32(As[rb + 8 * 32 + ca]));
        a0[2] = fbits(f_tf32(As[rb + ca2]));
        a0[3] = fbits(f_tf32(As[rb + 8 * 32 + ca2]));
        a1[0] = fbits(f_tf32(As[rb + 16 * 32 + ca]));
        a1[1] = fbits(f_tf32(As[rb + 24 * 32 + ca]));
        a1[2] = fbits(f_tf32(As[rb + 16 * 32 + ca2]));
        a1[3] = fbits(f_tf32(As[rb + 24 * 32 + ca2]));
        const float* Wk = Ws + (kk + la) * 128;
        const int cb = wn * 64 + lr;
        #pragma unroll
        for (int nt = 0; nt < 8; nt++) {
            const int cc = cb + ((nt ^ la) << 3);
            uint32_t b[2];
            b[0] = fbits(Wk[cc]);
            b[1] = fbits(Wk[4 * 128 + cc]);
            mma8(acc[0][nt], a0, b);
            mma8(acc[1][nt], a1, b);
        }
    }
}

// full 128x128x128 pipelined GEMM
__device__ __forceinline__ void gemm_pipe(
    float* sm, const float* Abase, int valid, float (&acc)[2][8][4],
    int wm, int wn, int la, int lr)
{
    stageA(sm, 0, Abase, valid);
    stageW(sm, 0, g_Wt);
    CP_COMMIT();
    #pragma unroll
    for (int kc = 0; kc < 4; kc++) {
        if (kc < 3) {
            stageA(sm, (kc + 1) & 1, Abase + (kc + 1) * 32, valid);
            stageW(sm, (kc + 1) & 1, g_Wt + (kc + 1) * 32 * DD);
            CP_COMMIT();
            asm volatile("cp.async.wait_group 1;\n" ::: "memory");
        } else {
            asm volatile("cp.async.wait_group 0;\n" ::: "memory");
        }
        __syncthreads();
        compute_chunk(sm + OFF_A + (kc & 1) * 4096, sm + OFF_W + (kc & 1) * 4096,
                      acc, wm, wn, la, lr);
        __syncthreads();
    }
}

// ---------------- init: gate table + tf32 W + bias.phi -----------------------
__global__ void init_kernel(const float* __restrict__ w1, const float* __restrict__ b1,
                            const float* __restrict__ w2, const float* __restrict__ b2,
                            const float* __restrict__ W, const float* __restrict__ bias,
                            const float* __restrict__ phi)
{
    const int t = threadIdx.x;
    const int gid = blockIdx.x * 256 + t;
    if (gid <= GT) {
        float d = (float)gid * (64.0f / (float)GT);
        float z = b2[0], bb = b1[0];
        #pragma unroll
        for (int g = 0; g < 32; g++) {
            float s = 1.0f / (1.0f + __expf(-(d * w1[g] + bb)));
            z += s * w2[g];
        }
        g_gate_table[gid] = 1.0f / (1.0f + __expf(-z));
    }
    const int b4 = gid * 4;
    if (b4 < DD * DD) {
        float4 v = *(const float4*)(W + b4);
        v.x = f_tf32(v.x); v.y = f_tf32(v.y); v.z = f_tf32(v.z); v.w = f_tf32(v.w);
        *(float4*)(g_Wt + b4) = v;
    }
    if (blockIdx.x == 0) {
        __shared__ float rn[128];
        if (t < 128) rn[t] = bias[t] * phi[t];
        __syncthreads();
        if (t == 0) {
            float an = 0.f;
            for (int i = 0; i < 128; i++) an += rn[i];
            g_Kbn = an;
        }
    }
}

// ---------------- kernel A: h_self + s_self ---------------------------------
__global__ void __launch_bounds__(256, 2) hself_kernel(
    const float* __restrict__ x_self, const float* __restrict__ bias,
    const float* __restrict__ phi)
{
    extern __shared__ float sm[];
    const int t = threadIdx.x, lane = t & 31, wid = t >> 5;
    const int wm = wid & 3, wn = wid >> 2, la = lane & 3, lr = lane >> 2;
    float* bias_s = sm + OFF_BIAS;
    float* ps = sm + OFF_PN;
    float* score_s = sm + OFF_SCORE;
    if (t < 128) { bias_s[t] = bias[t]; ps[t] = phi[128 + t]; score_s[t] = 0.f; }

    const int row_base = blockIdx.x * 128;
    int valid = NN - row_base; if (valid > 128) valid = 128;

    float acc[2][8][4] = {};
    gemm_pipe(sm, x_self + (size_t)row_base * DD, valid, acc, wm, wn, la, lr);

    // epilogue: write h_self directly; accumulate s_self partials
    float p0 = 0.f, p1 = 0.f, p2 = 0.f, p3 = 0.f;
    const int r = wm * 32 + lr;
    #pragma unroll
    for (int nt = 0; nt < 8; nt++) {
        const int c = wn * 64 + nt * 8 + la * 2;
        float b0 = bias_s[c], b1 = bias_s[c + 1];
        float pv0 = ps[c], pv1 = ps[c + 1];
        float h00 = acc[0][nt][0] + b0, h01 = acc[0][nt][1] + b1;
        float h10 = acc[0][nt][2] + b0, h11 = acc[0][nt][3] + b1;
        float h20 = acc[1][nt][0] + b0, h21 = acc[1][nt][1] + b1;
        float h30 = acc[1][nt][2] + b0, h31 = acc[1][nt][3] + b1;
        if (r      < valid) *(float2*)(g_hself + (size_t)(row_base + r     ) * DD + c) = make_float2(h00, h01);
        if (r + 8  < valid) *(float2*)(g_hself + (size_t)(row_base + r + 8 ) * DD + c) = make_float2(h10, h11);
        if (r + 16 < valid) *(float2*)(g_hself + (size_t)(row_base + r + 16) * DD + c) = make_float2(h20, h21);
        if (r + 24 < valid) *(float2*)(g_hself + (size_t)(row_base + r + 24) * DD + c) = make_float2(h30, h31);
        p0 += h00 * pv0 + h01 * pv1;
        p1 += h10 * pv0 + h11 * pv1;
        p2 += h20 * pv0 + h21 * pv1;
        p3 += h30 * pv0 + h31 * pv1;
    }
    #pragma unroll
    for (int off = 1; off <= 2; off <<= 1) {
        p0 += __shfl_xor_sync(0xffffffffu, p0, off);
        p1 += __shfl_xor_sync(0xffffffffu, p1, off);
        p2 += __shfl_xor_sync(0xffffffffu, p2, off);
        p3 += __shfl_xor_sync(0xffffffffu, p3, off);
    }
    if (la == 0) {
        atomicAdd(&score_s[r], p0);
        atomicAdd(&score_s[r + 8], p1);
        atomicAdd(&score_s[r + 16], p2);
        atomicAdd(&score_s[r + 24], p3);
    }
    __syncthreads();
    if (t < 128 && t < valid) g_sself[row_base + t] = score_s[t];
}

// ---------------- kernel B: fused neighbor GEMM + attention -----------------
__global__ void __launch_bounds__(256, 2) fused_kernel(
    const float* __restrict__ x_nb, const float* __restrict__ bias,
    const float* __restrict__ phi, const float* __restrict__ deg,
    const float* __restrict__ wsp, const float* __restrict__ wnp,
    float* __restrict__ out)
{
    extern __shared__ float sm[];
    const int t = threadIdx.x, lane = t & 31, wid = t >> 5;
    const int wm = wid & 3, wn = wid >> 2, la = lane & 3, lr = lane >> 2;
    float* pn = sm + OFF_PN;
    float* bias_s = sm + OFF_BIAS;
    float* gate_s = sm + OFF_GATE;
    float* score_s = sm + OFF_SCORE;
    float* attg = sm + OFF_ATT;
    float* ni = sm + OFF_NI;
    float* gsumS = sm + OFF_GS;

    const int node0 = blockIdx.x * 4;
    if (t < 128) {
        pn[t] = phi[t];
        bias_s[t] = bias[t];
        float d = deg[(size_t)node0 * KNB + t];
        float u = fminf(fmaxf(d * ((float)GT / 64.0f), 0.0f), (float)GT - 0.001f);
        int i = (int)u; float f = u - (float)i;
        float g0 = g_gate_table[i];
        gate_s[t] = g0 + (g_gate_table[i + 1] - g0) * f;
        score_s[t] = g_Kbn + g_sself[node0 + (t >> 5)];
    }

    float acc[2][8][4] = {};
    gemm_pipe(sm, x_nb + (size_t)node0 * KNB * DD, 128, acc, wm, wn, la, lr);

    // ---- score partials: acc . phi_n ----
    float p0 = 0.f, p1 = 0.f, p2 = 0.f, p3 = 0.f;
    #pragma unroll
    for (int nt = 0; nt < 8; nt++) {
        const int c = wn * 64 + nt * 8 + la * 2;
        float pv0 = pn[c], pv1 = pn[c + 1];
        p0 += acc[0][nt][0] * pv0 + acc[0][nt][1] * pv1;
        p1 += acc[0][nt][2] * pv0 + acc[0][nt][3] * pv1;
        p2 += acc[1][nt][0] * pv0 + acc[1][nt][1] * pv1;
        p3 += acc[1][nt][2] * pv0 + acc[1][nt][3] * pv1;
    }
    #pragma unroll
    for (int off = 1; off <= 2; off <<= 1) {
        p0 += __shfl_xor_sync(0xffffffffu, p0, off);
        p1 += __shfl_xor_sync(0xffffffffu, p1, off);
        p2 += __shfl_xor_sync(0xffffffffu, p2, off);
        p3 += __shfl_xor_sync(0xffffffffu, p3, off);
    }
    if (la == 0) {
        const int r = wm * 32 + lr;
        atomicAdd(&score_s[r], p0);
        atomicAdd(&score_s[r + 8], p1);
        atomicAdd(&score_s[r + 16], p2);
        atomicAdd(&score_s[r + 24], p3);
    }
    __syncthreads();

    // ---- leaky + softmax + gate fold (warp per node) ----
    if (wid < 4) {
        const int rr = wid * 32 + lane;
        float s = score_s[rr];
        s = (s > 0.f) ? s : 0.2f * s;
        float m = s;
        #pragma unroll
        for (int off = 16; off; off >>= 1) m = fmaxf(m, __shfl_xor_sync(0xffffffffu, m, off));
        float e = __expf(s - m);
        float ss = e;
        #pragma unroll
        for (int off = 16; off; off >>= 1) ss += __shfl_xor_sync(0xffffffffu, ss, off);
        float a = (e / ss) * gate_s[rr];
        attg[rr] = a;
        float gs = a;
        #pragma unroll
        for (int off = 16; off; off >>= 1) gs += __shfl_xor_sync(0xffffffffu, gs, off);
        if (lane == 0) gsumS[wid] = gs;
    }
    __syncthreads();

    // ---- weighted neighbor sum from registers ----
    const float w0 = attg[wm * 32 + lr];
    const float w1 = attg[wm * 32 + lr + 8];
    const float w2 = attg[wm * 32 + lr + 16];
    const float w3 = attg[wm * 32 + lr + 24];
    #pragma unroll
    for (int nt = 0; nt < 8; nt++) {
        float n0 = w0 * acc[0][nt][0] + w1 * acc[0][nt][2]
                 + w2 * acc[1][nt][0] + w3 * acc[1][nt][2];
        float n1 = w0 * acc[0][nt][1] + w1 * acc[0][nt][3]
                 + w2 * acc[1][nt][1] + w3 * acc[1][nt][3];
        #pragma unroll
        for (int off = 4; off <= 16; off <<= 1) {
            n0 += __shfl_xor_sync(0xffffffffu, n0, off);
            n1 += __shfl_xor_sync(0xffffffffu, n1, off);
        }
        if (lr == 0) {
            const int c = wn * 64 + nt * 8 + la * 2;
            ni[wm * 128 + c] = n0;
            ni[wm * 128 + c + 1] = n1;
        }
    }
    __syncthreads();

    // ---- final: relu(ws*h_self + wn*(ni + bias*gsum)) ----
    {
        const float wsv = wsp[0], wnv = wnp[0];
        const int row = t >> 6;
        const int c = (t & 63) * 2;
        const float gs = gsumS[row];
        const size_t gr = (size_t)(node0 + row) * DD + c;
        float2 hv = *(const float2*)(g_hself + gr);
        float n0 = ni[row * 128 + c] + bias_s[c] * gs;
        float n1 = ni[row * 128 + c + 1] + bias_s[c + 1] * gs;
        float o0 = wsv * hv.x + wnv * n0;
        float o1 = wsv * hv.y + wnv * n1;
        o0 = (o0 > 0.f) ? o0 : 0.f;
        o1 = (o1 > 0.f) ? o1 : 0.f;
        *(float2*)(out + gr) = make_float2(o0, o1);
    }
}

// ---------------- launch -----------------------------------------------------
extern "C" void kernel_launch(void* const* d_in, const int* in_sizes, int n_in,
                              void* d_out, int out_size)
{
    const float* x_self = (const float*)d_in[0];
    const float* x_nb   = (const float*)d_in[1];
    const float* deg    = (const float*)d_in[2];
    const float* W      = (const float*)d_in[3];
    const float* bias   = (const float*)d_in[4];
    const float* phi    = (const float*)d_in[5];
    const float* w1     = (const float*)d_in[6];
    const float* b1     = (const float*)d_in[7];
    const float* w2     = (const float*)d_in[8];
    const float* b2     = (const float*)d_in[9];
    const float* wsp    = (const float*)d_in[10];
    const float* wnp    = (const float*)d_in[11];
    float* out = (float*)d_out;

    cudaFuncSetAttribute(hself_kernel, cudaFuncAttributeMaxDynamicSharedMemorySize, SMEM_BYTES);
    cudaFuncSetAttribute(fused_kernel, cudaFuncAttributeMaxDynamicSharedMemorySize, SMEM_BYTES);

    init_kernel<<<17, 256>>>(w1, b1, w2, b2, W, bias, phi);
    hself_kernel<<<(NN + 127) / 128, 256, SMEM_BYTES>>>(x_self, bias, phi);
    fused_kernel<<<NN / 4, 256, SMEM_BYTES>>>(x_nb, bias, phi, deg, wsp, wnp, out);
}

// round 7
// speedup vs baseline: 2.3522x; 1.3246x over previous
#include <cuda_runtime.h>
#include <cuda_fp16.h>
#include <cstdint>

#define NN 20000
#define KNB 32
#define DD 128
#define GT 4096

// ---------------- device scratch (no runtime allocation) --------------------
__device__ float g_gate_table[GT + 1];
__device__ __align__(16) __half g_Wh[128 * 144];  // fp16 W image, [n][k-interleaved], 288B rows
__device__ float g_hself[NN * DD];
__device__ float g_sself[NN];
__device__ float g_Kbn;

// ---------------- smem layout (bytes) ---------------------------------------
// A: 2 buffers x (128 rows x 160B) = 40960
// W: 36864 (128 rows x 288B)
// epilogue floats: 1296 x 4 = 5184
#define A_STRIDE_F 40           // floats per A row (32 data + 8 pad)
#define A_BUF_B   20480
#define W_OFF_B   40960
#define EP_OFF_B  77824
#define SMEM_TOTAL 83008
// epilogue float offsets (relative to EP region)
#define PN_O      0
#define BIAS_O    128
#define SC2_O     256
#define ATT_O     512
#define GATE_O    640
#define NI_O      768
#define GSUM_O    1280
#define SSELF_O   1288

// ---------------- helpers ----------------------------------------------------
__device__ __forceinline__ uint32_t s2u(const void* p) {
    return (uint32_t)__cvta_generic_to_shared(p);
}
__device__ __forceinline__ void cp16p(uint32_t sa, const float* g, bool v) {
    int sz = v ? 16 : 0;
    asm volatile("cp.async.cg.shared.global [%0], [%1], 16, %2;" :: "r"(sa), "l"(g), "r"(sz));
}
#define CP_COMMIT() asm volatile("cp.async.commit_group;" ::: "memory")
#define CP_WAIT1()  asm volatile("cp.async.wait_group 1;" ::: "memory")
#define CP_WAIT0()  asm volatile("cp.async.wait_group 0;" ::: "memory")

__device__ __forceinline__ void mma16(float* c, const uint32_t* a, uint32_t b0, uint32_t b1) {
    asm volatile(
        "mma.sync.aligned.m16n8k16.row.col.f32.f16.f16.f32 "
        "{%0,%1,%2,%3}, {%4,%5,%6,%7}, {%8,%9}, {%0,%1,%2,%3};\n"
        : "+f"(c[0]), "+f"(c[1]), "+f"(c[2]), "+f"(c[3])
        : "r"(a[0]), "r"(a[1]), "r"(a[2]), "r"(a[3]), "r"(b0), "r"(b1));
}
__device__ __forceinline__ uint32_t pack2(float lo, float hi) {
    __half2 h = __floats2half2_rn(lo, hi);
    return *(uint32_t*)&h;
}

// ---------------- pipeline stages -------------------------------------------
__device__ __forceinline__ void stageA(uint32_t smem_base, int buf,
                                       const float* __restrict__ Ag, int valid) {
    const int t = threadIdx.x;
    const uint32_t base = smem_base + buf * A_BUF_B;
    #pragma unroll
    for (int i = 0; i < 4; i++) {
        int e = t + i * 256;
        int row = e >> 3, c4 = (e & 7) << 2;
        cp16p(base + row * 160 + c4 * 4, Ag + row * DD + c4, row < valid);
    }
}

// compute one k32 chunk (two k16 sub-steps) into acc
__device__ __forceinline__ void compute_chunk(
    const float* __restrict__ As, const char* __restrict__ Wb, int kc,
    float (&acc)[2][8][4], int wm, int wn, int lane)
{
    const int q2 = (lane & 3) * 2;
    const int lr = lane >> 2;
    const int r0 = wm * 32 + lr;
    #pragma unroll
    for (int s = 0; s < 2; s++) {
        const int kk = s * 16;
        float2 A00 = *(const float2*)(As + (r0     ) * A_STRIDE_F + kk + q2);
        float2 A01 = *(const float2*)(As + (r0 +  8) * A_STRIDE_F + kk + q2);
        float2 A02 = *(const float2*)(As + (r0     ) * A_STRIDE_F + kk + q2 + 8);
        float2 A03 = *(const float2*)(As + (r0 +  8) * A_STRIDE_F + kk + q2 + 8);
        float2 A10 = *(const float2*)(As + (r0 + 16) * A_STRIDE_F + kk + q2);
        float2 A11 = *(const float2*)(As + (r0 + 24) * A_STRIDE_F + kk + q2);
        float2 A12 = *(const float2*)(As + (r0 + 16) * A_STRIDE_F + kk + q2 + 8);
        float2 A13 = *(const float2*)(As + (r0 + 24) * A_STRIDE_F + kk + q2 + 8);
        uint32_t a0[4], a1[4];
        a0[0] = pack2(A00.x, A00.y); a0[1] = pack2(A01.x, A01.y);
        a0[2] = pack2(A02.x, A02.y); a0[3] = pack2(A03.x, A03.y);
        a1[0] = pack2(A10.x, A10.y); a1[1] = pack2(A11.x, A11.y);
        a1[2] = pack2(A12.x, A12.y); a1[3] = pack2(A13.x, A13.y);
        const int coff = (kc * 2 + s) * 32 + q2 * 4;
        #pragma unroll
        for (int nt = 0; nt < 8; nt++) {
            const int n = wn * 64 + nt * 8 + lr;
            uint2 b = *(const uint2*)(Wb + n * 288 + coff);
            mma16(acc[0][nt], a0, b.x, b.y);
            mma16(acc[1][nt], a1, b.x, b.y);
        }
    }
}

// full 128x128x128 pipelined GEMM (W resident, A double-buffered)
__device__ __forceinline__ void gemm_pipe(
    char* smc, uint32_t smem_base, const float* __restrict__ Abase, int valid,
    float (&acc)[2][8][4], int wm, int wn, int lane)
{
    const int t = threadIdx.x;
    // W copy (entire 36864B, once)
    #pragma unroll
    for (int i = 0; i < 9; i++) {
        int e = t + i * 256;
        cp16p(smem_base + W_OFF_B + e * 16,
              (const float*)((const char*)g_Wh + e * 16), true);
    }
    stageA(smem_base, 0, Abase, valid);
    CP_COMMIT();

    const char* Wb = smc + W_OFF_B;
    #pragma unroll
    for (int kc = 0; kc < 4; kc++) {
        if (kc < 3) {
            stageA(smem_base, (kc + 1) & 1, Abase + (kc + 1) * 32, valid);
            CP_COMMIT();
            CP_WAIT1();
        } else {
            CP_WAIT0();
        }
        __syncthreads();
        compute_chunk((const float*)(smc + (kc & 1) * A_BUF_B), Wb, kc,
                      acc, wm, wn, lane);
        __syncthreads();
    }
}

// ---------------- init: gate table + fp16 W image + bias.phi -----------------
__global__ void init_kernel(const float* __restrict__ w1, const float* __restrict__ b1,
                            const float* __restrict__ w2, const float* __restrict__ b2,
                            const float* __restrict__ W, const float* __restrict__ bias,
                            const float* __restrict__ phi)
{
    const int t = threadIdx.x;
    const int gid = blockIdx.x * 256 + t;
    if (gid <= GT) {
        float d = (float)gid * (64.0f / (float)GT);
        float z = b2[0], bb = b1[0];
        #pragma unroll
        for (int g = 0; g < 32; g++) {
            float s = 1.0f / (1.0f + __expf(-(d * w1[g] + bb)));
            z += s * w2[g];
        }
        g_gate_table[gid] = 1.0f / (1.0f + __expf(-z));
    }
    // fp16 W image: row n, chunk c (k16), quad q -> halves {k0,k0+1,k0+8,k0+9}
    if (gid < 4096) {
        int n = gid >> 5, c = (gid >> 2) & 7, q = gid & 3;
        int k0 = c * 16 + q * 2;
        __half2 h0 = __floats2half2_rn(W[k0 * DD + n],       W[(k0 + 1) * DD + n]);
        __half2 h1 = __floats2half2_rn(W[(k0 + 8) * DD + n], W[(k0 + 9) * DD + n]);
        *(__half2*)(g_Wh + n * 144 + c * 16 + q * 4)     = h0;
        *(__half2*)(g_Wh + n * 144 + c * 16 + q * 4 + 2) = h1;
    }
    if (gid < 1024) {   // zero pad halves (never read, but deterministic)
        int n = gid >> 3, j = gid & 7;
        *(uint32_t*)(g_Wh + n * 144 + 128 + j * 2) = 0;
    }
    if (blockIdx.x == 0) {
        __shared__ float rn[128];
        if (t < 128) rn[t] = bias[t] * phi[t];
        __syncthreads();
        if (t == 0) {
            float an = 0.f;
            for (int i = 0; i < 128; i++) an += rn[i];
            g_Kbn = an;
        }
    }
}

// ---------------- kernel A: h_self + s_self ---------------------------------
__global__ void __launch_bounds__(256, 2) hself_kernel(
    const float* __restrict__ x_self, const float* __restrict__ bias,
    const float* __restrict__ phi)
{
    extern __shared__ char smc[];
    const uint32_t smem_base = s2u(smc);
    float* smf = (float*)(smc + EP_OFF_B);
    const int t = threadIdx.x, lane = t & 31, wid = t >> 5;
    const int wm = wid & 3, wn = wid >> 2, la = lane & 3, lr = lane >> 2;
    float* bias_s = smf + BIAS_O;
    float* ps = smf + PN_O;
    float* score_s = smf + SC2_O;
    if (t < 128) { bias_s[t] = bias[t]; ps[t] = phi[128 + t]; score_s[t] = 0.f; }

    const int row_base = blockIdx.x * 128;
    int valid = NN - row_base; if (valid > 128) valid = 128;

    float acc[2][8][4] = {};
    gemm_pipe(smc, smem_base, x_self + (size_t)row_base * DD, valid, acc, wm, wn, lane);

    float p0 = 0.f, p1 = 0.f, p2 = 0.f, p3 = 0.f;
    const int r = wm * 32 + lr;
    #pragma unroll
    for (int nt = 0; nt < 8; nt++) {
        const int c = wn * 64 + nt * 8 + la * 2;
        float b0 = bias_s[c], b1 = bias_s[c + 1];
        float pv0 = ps[c], pv1 = ps[c + 1];
        float h00 = acc[0][nt][0] + b0, h01 = acc[0][nt][1] + b1;
        float h10 = acc[0][nt][2] + b0, h11 = acc[0][nt][3] + b1;
        float h20 = acc[1][nt][0] + b0, h21 = acc[1][nt][1] + b1;
        float h30 = acc[1][nt][2] + b0, h31 = acc[1][nt][3] + b1;
        if (r      < valid) *(float2*)(g_hself + (size_t)(row_base + r     ) * DD + c) = make_float2(h00, h01);
        if (r + 8  < valid) *(float2*)(g_hself + (size_t)(row_base + r + 8 ) * DD + c) = make_float2(h10, h11);
        if (r + 16 < valid) *(float2*)(g_hself + (size_t)(row_base + r + 16) * DD + c) = make_float2(h20, h21);
        if (r + 24 < valid) *(float2*)(g_hself + (size_t)(row_base + r + 24) * DD + c) = make_float2(h30, h31);
        p0 += h00 * pv0 + h01 * pv1;
        p1 += h10 * pv0 + h11 * pv1;
        p2 += h20 * pv0 + h21 * pv1;
        p3 += h30 * pv0 + h31 * pv1;
    }
    #pragma unroll
    for (int off = 1; off <= 2; off <<= 1) {
        p0 += __shfl_xor_sync(0xffffffffu, p0, off);
        p1 += __shfl_xor_sync(0xffffffffu, p1, off);
        p2 += __shfl_xor_sync(0xffffffffu, p2, off);
        p3 += __shfl_xor_sync(0xffffffffu, p3, off);
    }
    if (la == 0) {
        atomicAdd(&score_s[r], p0);
        atomicAdd(&score_s[r + 8], p1);
        atomicAdd(&score_s[r + 16], p2);
        atomicAdd(&score_s[r + 24], p3);
    }
    __syncthreads();
    if (t < 128 && t < valid) g_sself[row_base + t] = score_s[t];
}

// ---------------- kernel B: fused neighbor GEMM + attention -----------------
__global__ void __launch_bounds__(256, 2) fused_kernel(
    const float* __restrict__ x_nb, const float* __restrict__ bias,
    const float* __restrict__ phi, const float* __restrict__ deg,
    const float* __restrict__ wsp, const float* __restrict__ wnp,
    float* __restrict__ out)
{
    extern __shared__ char smc[];
    const uint32_t smem_base = s2u(smc);
    float* smf = (float*)(smc + EP_OFF_B);
    const int t = threadIdx.x, lane = t & 31, wid = t >> 5;
    const int wm = wid & 3, wn = wid >> 2, la = lane & 3, lr = lane >> 2;
    float* pn = smf + PN_O;
    float* bias_s = smf + BIAS_O;
    float* gate_s = smf + GATE_O;
    float* score_s = smf + SC2_O;
    float* attg = smf + ATT_O;
    float* ni = smf + NI_O;
    float* gsumS = smf + GSUM_O;

    const int node0 = blockIdx.x * 4;
    if (t < 128) {
        pn[t] = phi[t];
        bias_s[t] = bias[t];
        float d = deg[(size_t)node0 * KNB + t];
        float u = fminf(fmaxf(d * ((float)GT / 64.0f), 0.0f), (float)GT - 0.001f);
        int i = (int)u; float f = u - (float)i;
        float g0 = g_gate_table[i];
        gate_s[t] = g0 + (g_gate_table[i + 1] - g0) * f;
        score_s[t] = g_Kbn + g_sself[node0 + (t >> 5)];
    }

    float acc[2][8][4] = {};
    gemm_pipe(smc, smem_base, x_nb + (size_t)node0 * KNB * DD, 128, acc, wm, wn, lane);

    // ---- score partials: acc . phi_n ----
    float p0 = 0.f, p1 = 0.f, p2 = 0.f, p3 = 0.f;
    #pragma unroll
    for (int nt = 0; nt < 8; nt++) {
        const int c = wn * 64 + nt * 8 + la * 2;
        float pv0 = pn[c], pv1 = pn[c + 1];
        p0 += acc[0][nt][0] * pv0 + acc[0][nt][1] * pv1;
        p1 += acc[0][nt][2] * pv0 + acc[0][nt][3] * pv1;
        p2 += acc[1][nt][0] * pv0 + acc[1][nt][1] * pv1;
        p3 += acc[1][nt][2] * pv0 + acc[1][nt][3] * pv1;
    }
    #pragma unroll
    for (int off = 1; off <= 2; off <<= 1) {
        p0 += __shfl_xor_sync(0xffffffffu, p0, off);
        p1 += __shfl_xor_sync(0xffffffffu, p1, off);
        p2 += __shfl_xor_sync(0xffffffffu, p2, off);
        p3 += __shfl_xor_sync(0xffffffffu, p3, off);
    }
    if (la == 0) {
        const int r = wm * 32 + lr;
        atomicAdd(&score_s[r], p0);
        atomicAdd(&score_s[r + 8], p1);
        atomicAdd(&score_s[r + 16], p2);
        atomicAdd(&score_s[r + 24], p3);
    }
    __syncthreads();

    // ---- leaky + softmax + gate fold (warp per node) ----
    if (wid < 4) {
        const int rr = wid * 32 + lane;
        float s = score_s[rr];
        s = (s > 0.f) ? s : 0.2f * s;
        float m = s;
        #pragma unroll
        for (int off = 16; off; off >>= 1) m = fmaxf(m, __shfl_xor_sync(0xffffffffu, m, off));
        float e = __expf(s - m);
        float ss = e;
        #pragma unroll
        for (int off = 16; off; off >>= 1) ss += __shfl_xor_sync(0xffffffffu, ss, off);
        float a = (e / ss) * gate_s[rr];
        attg[rr] = a;
        float gs = a;
        #pragma unroll
        for (int off = 16; off; off >>= 1) gs += __shfl_xor_sync(0xffffffffu, gs, off);
        if (lane == 0) gsumS[wid] = gs;
    }
    __syncthreads();

    // ---- weighted neighbor sum from registers ----
    const float w0 = attg[wm * 32 + lr];
    const float w1 = attg[wm * 32 + lr + 8];
    const float w2 = attg[wm * 32 + lr + 16];
    const float w3 = attg[wm * 32 + lr + 24];
    #pragma unroll
    for (int nt = 0; nt < 8; nt++) {
        float n0 = w0 * acc[0][nt][0] + w1 * acc[0][nt][2]
                 + w2 * acc[1][nt][0] + w3 * acc[1][nt][2];
        float n1 = w0 * acc[0][nt][1] + w1 * acc[0][nt][3]
                 + w2 * acc[1][nt][1] + w3 * acc[1][nt][3];
        #pragma unroll
        for (int off = 4; off <= 16; off <<= 1) {
            n0 += __shfl_xor_sync(0xffffffffu, n0, off);
            n1 += __shfl_xor_sync(0xffffffffu, n1, off);
        }
        if (lr == 0) {
            const int c = wn * 64 + nt * 8 + la * 2;
            ni[wm * 128 + c] = n0;
            ni[wm * 128 + c + 1] = n1;
        }
    }
    __syncthreads();

    // ---- final: relu(ws*h_self + wn*(ni + bias*gsum)) ----
    {
        const float wsv = wsp[0], wnv = wnp[0];
        const int row = t >> 6;
        const int c = (t & 63) * 2;
        const float gs = gsumS[row];
        const size_t gr = (size_t)(node0 + row) * DD + c;
        float2 hv = *(const float2*)(g_hself + gr);
        float n0 = ni[row * 128 + c] + bias_s[c] * gs;
        float n1 = ni[row * 128 + c + 1] + bias_s[c + 1] * gs;
        float o0 = wsv * hv.x + wnv * n0;
        float o1 = wsv * hv.y + wnv * n1;
        o0 = (o0 > 0.f) ? o0 : 0.f;
        o1 = (o1 > 0.f) ? o1 : 0.f;
        *(float2*)(out + gr) = make_float2(o0, o1);
    }
}

// ---------------- launch -----------------------------------------------------
extern "C" void kernel_launch(void* const* d_in, const int* in_sizes, int n_in,
                              void* d_out, int out_size)
{
    const float* x_self = (const float*)d_in[0];
    const float* x_nb   = (const float*)d_in[1];
    const float* deg    = (const float*)d_in[2];
    const float* W      = (const float*)d_in[3];
    const float* bias   = (const float*)d_in[4];
    const float* phi    = (const float*)d_in[5];
    const float* w1     = (const float*)d_in[6];
    const float* b1     = (const float*)d_in[7];
    const float* w2     = (const float*)d_in[8];
    const float* b2     = (const float*)d_in[9];
    const float* wsp    = (const float*)d_in[10];
    const float* wnp    = (const float*)d_in[11];
    float* out = (float*)d_out;

    cudaFuncSetAttribute(hself_kernel, cudaFuncAttributeMaxDynamicSharedMemorySize, SMEM_TOTAL);
    cudaFuncSetAttribute(fused_kernel, cudaFuncAttributeMaxDynamicSharedMemorySize, SMEM_TOTAL);

    init_kernel<<<17, 256>>>(w1, b1, w2, b2, W, bias, phi);
    hself_kernel<<<(NN + 127) / 128, 256, SMEM_TOTAL>>>(x_self, bias, phi);
    fused_kernel<<<NN / 4, 256, SMEM_TOTAL>>>(x_nb, bias, phi, deg, wsp, wnp, out);
}

// round 10
// speedup vs baseline: 2.6793x; 1.1390x over previous
#include <cuda_runtime.h>
#include <cuda_fp16.h>
#include <cstdint>

#define NN 20000
#define KNB 32
#define DD 128
#define GT 4096

// ---------------- device scratch (no runtime allocation) --------------------
__device__ float g_gate_table[GT + 1];
__device__ __align__(16) __half g_Wh[128 * 144];  // fp16 W image, [n][k-interleaved], 288B rows
__device__ __align__(16) float g_u[DD];           // W @ phi_n
__device__ __align__(16) float g_v[DD];           // W @ phi_s
__device__ float g_c0, g_c1;                      // b.phi_n, b.phi_s
__device__ __align__(16) float g_z[NN * DD];      // ws*x_self + wn*y
__device__ float g_beta[NN];                      // ws + wn*gs

// ---------------- K3 smem layout (bytes) — same as R6/R7 GEMM ---------------
#define A_STRIDE_F 40
#define A_BUF_B   20480
#define W_OFF_B   40960
#define EP_OFF_B  77824
#define SMEM_TOTAL 83008

// ---------------- K2 smem layout (float offsets) ----------------------------
#define XSTR  132
#define X_O   0          // 2 nodes x 32 rows x 132
#define XS_O  8448       // 2 x 128 x_self rows
#define U_O   8704
#define V_O   8832
#define SC_O  8960       // 64 raw scores
#define SS_O  9024       // 2 s_self dots
#define ATT_O 9032       // 64 att*gate
#define GD_O  9096       // 64 deg
#define K2_FLOATS 9160
#define K2_SMEM (K2_FLOATS * 4)

// ---------------- helpers ----------------------------------------------------
__device__ __forceinline__ uint32_t s2u(const void* p) {
    return (uint32_t)__cvta_generic_to_shared(p);
}
__device__ __forceinline__ void cp16p(uint32_t sa, const float* g, bool v) {
    int sz = v ? 16 : 0;
    asm volatile("cp.async.cg.shared.global [%0], [%1], 16, %2;" :: "r"(sa), "l"(g), "r"(sz));
}
#define CP_COMMIT() asm volatile("cp.async.commit_group;" ::: "memory")
#define CP_WAIT1()  asm volatile("cp.async.wait_group 1;" ::: "memory")
#define CP_WAIT0()  asm volatile("cp.async.wait_group 0;" ::: "memory")

__device__ __forceinline__ void mma16(float* c, const uint32_t* a, uint32_t b0, uint32_t b1) {
    asm volatile(
        "mma.sync.aligned.m16n8k16.row.col.f32.f16.f16.f32 "
        "{%0,%1,%2,%3}, {%4,%5,%6,%7}, {%8,%9}, {%0,%1,%2,%3};\n"
        : "+f"(c[0]), "+f"(c[1]), "+f"(c[2]), "+f"(c[3])
        : "r"(a[0]), "r"(a[1]), "r"(a[2]), "r"(a[3]), "r"(b0), "r"(b1));
}
__device__ __forceinline__ uint32_t pack2(float lo, float hi) {
    __half2 h = __floats2half2_rn(lo, hi);
    return *(uint32_t*)&h;
}

// ---------------- K3 GEMM machinery (proven in R6/R7) ------------------------
__device__ __forceinline__ void stageA(uint32_t smem_base, int buf,
                                       const float* __restrict__ Ag, int valid) {
    const int t = threadIdx.x;
    const uint32_t base = smem_base + buf * A_BUF_B;
    #pragma unroll
    for (int i = 0; i < 4; i++) {
        int e = t + i * 256;
        int row = e >> 3, c4 = (e & 7) << 2;
        cp16p(base + row * 160 + c4 * 4, Ag + row * DD + c4, row < valid);
    }
}

__device__ __forceinline__ void compute_chunk(
    const float* __restrict__ As, const char* __restrict__ Wb, int kc,
    float (&acc)[2][8][4], int wm, int wn, int lane)
{
    const int q2 = (lane & 3) * 2;
    const int lr = lane >> 2;
    const int r0 = wm * 32 + lr;
    #pragma unroll
    for (int s = 0; s < 2; s++) {
        const int kk = s * 16;
        float2 A00 = *(const float2*)(As + (r0     ) * A_STRIDE_F + kk + q2);
        float2 A01 = *(const float2*)(As + (r0 +  8) * A_STRIDE_F + kk + q2);
        float2 A02 = *(const float2*)(As + (r0     ) * A_STRIDE_F + kk + q2 + 8);
        float2 A03 = *(const float2*)(As + (r0 +  8) * A_STRIDE_F + kk + q2 + 8);
        float2 A10 = *(const float2*)(As + (r0 + 16) * A_STRIDE_F + kk + q2);
        float2 A11 = *(const float2*)(As + (r0 + 24) * A_STRIDE_F + kk + q2);
        float2 A12 = *(const float2*)(As + (r0 + 16) * A_STRIDE_F + kk + q2 + 8);
        float2 A13 = *(const float2*)(As + (r0 + 24) * A_STRIDE_F + kk + q2 + 8);
        uint32_t a0[4], a1[4];
        a0[0] = pack2(A00.x, A00.y); a0[1] = pack2(A01.x, A01.y);
        a0[2] = pack2(A02.x, A02.y); a0[3] = pack2(A03.x, A03.y);
        a1[0] = pack2(A10.x, A10.y); a1[1] = pack2(A11.x, A11.y);
        a1[2] = pack2(A12.x, A12.y); a1[3] = pack2(A13.x, A13.y);
        const int coff = (kc * 2 + s) * 32 + q2 * 4;
        #pragma unroll
        for (int nt = 0; nt < 8; nt++) {
            const int n = wn * 64 + nt * 8 + lr;
            uint2 b = *(const uint2*)(Wb + n * 288 + coff);
            mma16(acc[0][nt], a0, b.x, b.y);
            mma16(acc[1][nt], a1, b.x, b.y);
        }
    }
}

__device__ __forceinline__ void gemm_pipe(
    char* smc, uint32_t smem_base, const float* __restrict__ Abase, int valid,
    float (&acc)[2][8][4], int wm, int wn, int lane)
{
    const int t = threadIdx.x;
    #pragma unroll
    for (int i = 0; i < 9; i++) {
        int e = t + i * 256;
        cp16p(smem_base + W_OFF_B + e * 16,
              (const float*)((const char*)g_Wh + e * 16), true);
    }
    stageA(smem_base, 0, Abase, valid);
    CP_COMMIT();

    const char* Wb = smc + W_OFF_B;
    #pragma unroll
    for (int kc = 0; kc < 4; kc++) {
        if (kc < 3) {
            stageA(smem_base, (kc + 1) & 1, Abase + (kc + 1) * 32, valid);
            CP_COMMIT();
            CP_WAIT1();
        } else {
            CP_WAIT0();
        }
        __syncthreads();
        compute_chunk((const float*)(smc + (kc & 1) * A_BUF_B), Wb, kc,
                      acc, wm, wn, lane);
        __syncthreads();
    }
}

// ---------------- K1: init (gate table, W image, u, v, c0, c1) ---------------
__global__ void init_kernel(const float* __restrict__ w1, const float* __restrict__ b1,
                            const float* __restrict__ w2, const float* __restrict__ b2,
                            const float* __restrict__ W, const float* __restrict__ bias,
                            const float* __restrict__ phi)
{
    __shared__ float sw1[32], sw2[32], rn[128], rs[128];
    const int t = threadIdx.x;
    const int gid = blockIdx.x * 256 + t;
    if (t < 32) { sw1[t] = w1[t]; sw2[t] = w2[t]; }
    __syncthreads();

    if (gid <= GT) {
        float d = (float)gid * (64.0f / (float)GT);
        float z = b2[0], bb = b1[0];
        #pragma unroll
        for (int g = 0; g < 32; g++) {
            float s = 1.0f / (1.0f + __expf(-(d * sw1[g] + bb)));
            z += s * sw2[g];
        }
        g_gate_table[gid] = 1.0f / (1.0f + __expf(-z));
    }
    // fp16 W image: row n, chunk c (k16), quad q -> halves {k0,k0+1,k0+8,k0+9}
    if (gid < 4096) {
        int n = gid >> 5, c = (gid >> 2) & 7, q = gid & 3;
        int k0 = c * 16 + q * 2;
        __half2 h0 = __floats2half2_rn(W[k0 * DD + n],       W[(k0 + 1) * DD + n]);
        __half2 h1 = __floats2half2_rn(W[(k0 + 8) * DD + n], W[(k0 + 9) * DD + n]);
        *(__half2*)(g_Wh + n * 144 + c * 16 + q * 4)     = h0;
        *(__half2*)(g_Wh + n * 144 + c * 16 + q * 4 + 2) = h1;
    }
    if (gid < 1024) {
        int n = gid >> 3, j = gid & 7;
        *(uint32_t*)(g_Wh + n * 144 + 128 + j * 2) = 0;
    }
    if (blockIdx.x == 0) {
        if (t < 128) {
            float ua = 0.f, va = 0.f;
            #pragma unroll 8
            for (int o = 0; o < 128; o++) {
                float w = W[t * DD + o];
                ua += w * phi[o];
                va += w * phi[DD + o];
            }
            g_u[t] = ua;
            g_v[t] = va;
            rn[t] = bias[t] * phi[t];
            rs[t] = bias[t] * phi[DD + t];
        }
        __syncthreads();
        if (t == 0) { float a = 0.f; for (int i = 0; i < 128; i++) a += rn[i]; g_c0 = a; }
        if (t == 32) { float a = 0.f; for (int i = 0; i < 128; i++) a += rs[i]; g_c1 = a; }
    }
}

// ---------------- K2: streaming attention pass (2 nodes / CTA) ---------------
// Differential-test version: NO cp.async — plain float4 loads only.
__global__ void __launch_bounds__(256) stream_kernel(
    const float* __restrict__ x_self, const float* __restrict__ x_nb,
    const float* __restrict__ deg,
    const float* __restrict__ wsp, const float* __restrict__ wnp)
{
    extern __shared__ float smf[];
    const int t = threadIdx.x, lane = t & 31, wid = t >> 5;
    const int node0 = blockIdx.x * 2;

    // ---- plain vectorized loads: x_nb tile, x_self rows, u, v, deg ----
    {
        const float4* Ab4 = (const float4*)(x_nb + (size_t)node0 * KNB * DD);
        #pragma unroll
        for (int i = 0; i < 8; i++) {
            int e = t + i * 256;
            int row = e >> 5, c4 = e & 31;
            float4 v = Ab4[row * 32 + c4];
            *(float4*)(smf + X_O + row * XSTR + c4 * 4) = v;
        }
        if (t < 64) {
            int row = t >> 5, c4 = t & 31;
            float4 v = *(const float4*)(x_self + (size_t)(node0 + row) * DD + c4 * 4);
            *(float4*)(smf + XS_O + row * DD + c4 * 4) = v;
        }
        if (t < 32) *(float4*)(smf + U_O + t * 4) = *(const float4*)(g_u + t * 4);
        if (t < 32) *(float4*)(smf + V_O + t * 4) = *(const float4*)(g_v + t * 4);
        if (t < 16) *(float4*)(smf + GD_O + t * 4) =
            *(const float4*)(deg + (size_t)node0 * KNB + t * 4);
    }
    __syncthreads();

    // ---- raw scores: x_nb . u  (warp w handles rows 8w..8w+7) ----
    float uv0 = smf[U_O + lane], uv1 = smf[U_O + lane + 32];
    float uv2 = smf[U_O + lane + 64], uv3 = smf[U_O + lane + 96];
    #pragma unroll
    for (int i = 0; i < 8; i++) {
        const int row = wid * 8 + i;
        const float* Xr = smf + X_O + row * XSTR;
        float p = Xr[lane] * uv0 + Xr[lane + 32] * uv1
                + Xr[lane + 64] * uv2 + Xr[lane + 96] * uv3;
        #pragma unroll
        for (int off = 16; off; off >>= 1)
            p += __shfl_xor_sync(0xffffffffu, p, off);
        if (lane == 0) smf[SC_O + row] = p;
    }
    // ---- s_self: x_self . v (warps 0,1) ----
    if (wid < 2) {
        const float* Xr = smf + XS_O + wid * DD;
        float p = Xr[lane] * smf[V_O + lane] + Xr[lane + 32] * smf[V_O + lane + 32]
                + Xr[lane + 64] * smf[V_O + lane + 64] + Xr[lane + 96] * smf[V_O + lane + 96];
        #pragma unroll
        for (int off = 16; off; off >>= 1)
            p += __shfl_xor_sync(0xffffffffu, p, off);
        if (lane == 0) smf[SS_O + wid] = p;
    }
    __syncthreads();

    const float wsv = wsp[0], wnv = wnp[0];

    // ---- leaky + softmax + gate (warp per node) ----
    if (wid < 2) {
        float s = smf[SC_O + wid * 32 + lane] + g_c0 + smf[SS_O + wid] + g_c1;
        s = (s > 0.f) ? s : 0.2f * s;
        float m = s;
        #pragma unroll
        for (int off = 16; off; off >>= 1)
            m = fmaxf(m, __shfl_xor_sync(0xffffffffu, m, off));
        float e = __expf(s - m);
        float ss = e;
        #pragma unroll
        for (int off = 16; off; off >>= 1)
            ss += __shfl_xor_sync(0xffffffffu, ss, off);
        float d = smf[GD_O + wid * 32 + lane];
        float u = fminf(fmaxf(d * ((float)GT / 64.0f), 0.0f), (float)GT - 0.001f);
        int ix = (int)u; float fr = u - (float)ix;
        float g0 = g_gate_table[ix];
        float gt = g0 + (g_gate_table[ix + 1] - g0) * fr;
        float a = (e / ss) * gt;
        smf[ATT_O + wid * 32 + lane] = a;
        float gs = a;
        #pragma unroll
        for (int off = 16; off; off >>= 1)
            gs += __shfl_xor_sync(0xffffffffu, gs, off);
        if (lane == 0) g_beta[node0 + wid] = wsv + wnv * gs;
    }
    __syncthreads();

    // ---- weighted neighbor sum + z write (128 threads per node) ----
    {
        const int node = t >> 7, c = t & 127;
        const float* Xn = smf + X_O + node * 32 * XSTR + c;
        const float* At = smf + ATT_O + node * 32;
        float y = 0.f;
        #pragma unroll
        for (int k = 0; k < 32; k++)
            y = fmaf(At[k], Xn[k * XSTR], y);
        float z = wsv * smf[XS_O + node * DD + c] + wnv * y;
        g_z[(size_t)(node0 + node) * DD + c] = z;
    }
}

// ---------------- K3: out = relu(z @ W + beta_n * b) -------------------------
__global__ void __launch_bounds__(256, 2) out_kernel(
    const float* __restrict__ bias, float* __restrict__ out)
{
    extern __shared__ char smc[];
    const uint32_t smem_base = s2u(smc);
    float* smf = (float*)(smc + EP_OFF_B);
    const int t = threadIdx.x, lane = t & 31, wid = t >> 5;
    const int wm = wid & 3, wn = wid >> 2, la = lane & 3, lr = lane >> 2;
    float* bias_s = smf;
    float* beta_s = smf + 128;

    const int row_base = blockIdx.x * 128;
    int valid = NN - row_base; if (valid > 128) valid = 128;

    if (t < 128) {
        bias_s[t] = bias[t];
        int gr = row_base + t;
        beta_s[t] = (gr < NN) ? g_beta[gr] : 0.f;
    }

    float acc[2][8][4] = {};
    gemm_pipe(smc, smem_base, g_z + (size_t)row_base * DD, valid, acc, wm, wn, lane);

    const int r = wm * 32 + lr;
    const float be0 = beta_s[r], be1 = beta_s[r + 8];
    const float be2 = beta_s[r + 16], be3 = beta_s[r + 24];
    #pragma unroll
    for (int nt = 0; nt < 8; nt++) {
        const int c = wn * 64 + nt * 8 + la * 2;
        const float b0 = bias_s[c], b1 = bias_s[c + 1];
        float o00 = acc[0][nt][0] + be0 * b0, o01 = acc[0][nt][1] + be0 * b1;
        float o10 = acc[0][nt][2] + be1 * b0, o11 = acc[0][nt][3] + be1 * b1;
        float o20 = acc[1][nt][0] + be2 * b0, o21 = acc[1][nt][1] + be2 * b1;
        float o30 = acc[1][nt][2] + be3 * b0, o31 = acc[1][nt][3] + be3 * b1;
        o00 = o00 > 0.f ? o00 : 0.f;  o01 = o01 > 0.f ? o01 : 0.f;
        o10 = o10 > 0.f ? o10 : 0.f;  o11 = o11 > 0.f ? o11 : 0.f;
        o20 = o20 > 0.f ? o20 : 0.f;  o21 = o21 > 0.f ? o21 : 0.f;
        o30 = o30 > 0.f ? o30 : 0.f;  o31 = o31 > 0.f ? o31 : 0.f;
        if (r      < valid) *(float2*)(out + (size_t)(row_base + r     ) * DD + c) = make_float2(o00, o01);
        if (r + 8  < valid) *(float2*)(out + (size_t)(row_base + r + 8 ) * DD + c) = make_float2(o10, o11);
        if (r + 16 < valid) *(float2*)(out + (size_t)(row_base + r + 16) * DD + c) = make_float2(o20, o21);
        if (r + 24 < valid) *(float2*)(out + (size_t)(row_base + r + 24) * DD + c) = make_float2(o30, o31);
    }
}

// ---------------- launch -----------------------------------------------------
extern "C" void kernel_launch(void* const* d_in, const int* in_sizes, int n_in,
                              void* d_out, int out_size)
{
    const float* x_self = (const float*)d_in[0];
    const float* x_nb   = (const float*)d_in[1];
    const float* deg    = (const float*)d_in[2];
    const float* W      = (const float*)d_in[3];
    const float* bias   = (const float*)d_in[4];
    const float* phi    = (const float*)d_in[5];
    const float* w1     = (const float*)d_in[6];
    const float* b1     = (const float*)d_in[7];
    const float* w2     = (const float*)d_in[8];
    const float* b2     = (const float*)d_in[9];
    const float* wsp    = (const float*)d_in[10];
    const float* wnp    = (const float*)d_in[11];
    float* out = (float*)d_out;

    cudaFuncSetAttribute(out_kernel, cudaFuncAttributeMaxDynamicSharedMemorySize, SMEM_TOTAL);

    init_kernel<<<17, 256>>>(w1, b1, w2, b2, W, bias, phi);
    stream_kernel<<<NN / 2, 256, K2_SMEM>>>(x_self, x_nb, deg, wsp, wnp);
    out_kernel<<<(NN + 127) / 128, 256, SMEM_TOTAL>>>(bias, out);
}

// round 12
// speedup vs baseline: 2.9547x; 1.1028x over previous
#include <cuda_runtime.h>
#include <cuda_fp16.h>
#include <cstdint>

#define NN 20000
#define KNB 32
#define DD 128
#define GT 4096
#define PAIRS 4            // node-pairs per K2 CTA

// ---------------- device scratch (no runtime allocation) --------------------
__device__ float g_gate_table[GT + 1];
__device__ __align__(16) __half g_Wh[128 * 144];  // fp16 W image, [n][k-interleaved], 288B rows
__device__ __align__(16) float g_u[DD];           // W @ phi_n
__device__ __align__(16) float g_v[DD];           // W @ phi_s
__device__ float g_c0, g_c1;                      // b.phi_n, b.phi_s
__device__ __align__(16) float g_z[NN * DD];      // ws*x_self + wn*y
__device__ float g_beta[NN];                      // ws + wn*gs

// ---------------- K3 smem layout (bytes) — same as R6/R7/R10 GEMM -----------
#define A_STRIDE_F 40
#define A_BUF_B   20480
#define W_OFF_B   40960
#define EP_OFF_B  77824
#define SMEM_TOTAL 83008

// ---------------- K2 smem layout (float offsets), single buffer -------------
#define XSTR   132
#define X_O    0            // 64 rows x 132
#define XS_O   8448         // 2 x 128 x_self rows
#define U_O    8704
#define V_O    8832
#define SC_O   8960         // 64 raw scores
#define SS_O   9024         // 2 s_self dots (pad 8)
#define ATT_O  9032         // 64 att*gate
#define K2_FLOATS 9096
#define K2_SMEM (K2_FLOATS * 4)

// ---------------- helpers ----------------------------------------------------
__device__ __forceinline__ uint32_t s2u(const void* p) {
    return (uint32_t)__cvta_generic_to_shared(p);
}
__device__ __forceinline__ void cp16p(uint32_t sa, const float* g, bool v) {
    int sz = v ? 16 : 0;
    asm volatile("cp.async.cg.shared.global [%0], [%1], 16, %2;" :: "r"(sa), "l"(g), "r"(sz));
}
#define CP_COMMIT() asm volatile("cp.async.commit_group;" ::: "memory")
#define CP_WAIT1()  asm volatile("cp.async.wait_group 1;" ::: "memory")
#define CP_WAIT0()  asm volatile("cp.async.wait_group 0;" ::: "memory")

__device__ __forceinline__ void mma16(float* c, const uint32_t* a, uint32_t b0, uint32_t b1) {
    asm volatile(
        "mma.sync.aligned.m16n8k16.row.col.f32.f16.f16.f32 "
        "{%0,%1,%2,%3}, {%4,%5,%6,%7}, {%8,%9}, {%0,%1,%2,%3};\n"
        : "+f"(c[0]), "+f"(c[1]), "+f"(c[2]), "+f"(c[3])
        : "r"(a[0]), "r"(a[1]), "r"(a[2]), "r"(a[3]), "r"(b0), "r"(b1));
}
__device__ __forceinline__ uint32_t pack2(float lo, float hi) {
    __half2 h = __floats2half2_rn(lo, hi);
    return *(uint32_t*)&h;
}

// ---------------- K3 GEMM machinery (proven in R6/R7/R10) --------------------
__device__ __forceinline__ void stageA(uint32_t smem_base, int buf,
                                       const float* __restrict__ Ag, int valid) {
    const int t = threadIdx.x;
    const uint32_t base = smem_base + buf * A_BUF_B;
    #pragma unroll
    for (int i = 0; i < 4; i++) {
        int e = t + i * 256;
        int row = e >> 3, c4 = (e & 7) << 2;
        cp16p(base + row * 160 + c4 * 4, Ag + row * DD + c4, row < valid);
    }
}

__device__ __forceinline__ void compute_chunk(
    const float* __restrict__ As, const char* __restrict__ Wb, int kc,
    float (&acc)[2][8][4], int wm, int wn, int lane)
{
    const int q2 = (lane & 3) * 2;
    const int lr = lane >> 2;
    const int r0 = wm * 32 + lr;
    #pragma unroll
    for (int s = 0; s < 2; s++) {
        const int kk = s * 16;
        float2 A00 = *(const float2*)(As + (r0     ) * A_STRIDE_F + kk + q2);
        float2 A01 = *(const float2*)(As + (r0 +  8) * A_STRIDE_F + kk + q2);
        float2 A02 = *(const float2*)(As + (r0     ) * A_STRIDE_F + kk + q2 + 8);
        float2 A03 = *(const float2*)(As + (r0 +  8) * A_STRIDE_F + kk + q2 + 8);
        float2 A10 = *(const float2*)(As + (r0 + 16) * A_STRIDE_F + kk + q2);
        float2 A11 = *(const float2*)(As + (r0 + 24) * A_STRIDE_F + kk + q2);
        float2 A12 = *(const float2*)(As + (r0 + 16) * A_STRIDE_F + kk + q2 + 8);
        float2 A13 = *(const float2*)(As + (r0 + 24) * A_STRIDE_F + kk + q2 + 8);
        uint32_t a0[4], a1[4];
        a0[0] = pack2(A00.x, A00.y); a0[1] = pack2(A01.x, A01.y);
        a0[2] = pack2(A02.x, A02.y); a0[3] = pack2(A03.x, A03.y);
        a1[0] = pack2(A10.x, A10.y); a1[1] = pack2(A11.x, A11.y);
        a1[2] = pack2(A12.x, A12.y); a1[3] = pack2(A13.x, A13.y);
        const int coff = (kc * 2 + s) * 32 + q2 * 4;
        #pragma unroll
        for (int nt = 0; nt < 8; nt++) {
            const int n = wn * 64 + nt * 8 + lr;
            uint2 b = *(const uint2*)(Wb + n * 288 + coff);
            mma16(acc[0][nt], a0, b.x, b.y);
            mma16(acc[1][nt], a1, b.x, b.y);
        }
    }
}

__device__ __forceinline__ void gemm_pipe(
    char* smc, uint32_t smem_base, const float* __restrict__ Abase, int valid,
    float (&acc)[2][8][4], int wm, int wn, int lane)
{
    const int t = threadIdx.x;
    #pragma unroll
    for (int i = 0; i < 9; i++) {
        int e = t + i * 256;
        cp16p(smem_base + W_OFF_B + e * 16,
              (const float*)((const char*)g_Wh + e * 16), true);
    }
    stageA(smem_base, 0, Abase, valid);
    CP_COMMIT();

    const char* Wb = smc + W_OFF_B;
    #pragma unroll
    for (int kc = 0; kc < 4; kc++) {
        if (kc < 3) {
            stageA(smem_base, (kc + 1) & 1, Abase + (kc + 1) * 32, valid);
            CP_COMMIT();
            CP_WAIT1();
        } else {
            CP_WAIT0();
        }
        __syncthreads();
        compute_chunk((const float*)(smc + (kc & 1) * A_BUF_B), Wb, kc,
                      acc, wm, wn, lane);
        __syncthreads();
    }
}

// ---------------- K1: init (gate table, W image, u, v, c0, c1) ---------------
__global__ void init_kernel(const float* __restrict__ w1, const float* __restrict__ b1,
                            const float* __restrict__ w2, const float* __restrict__ b2,
                            const float* __restrict__ W, const float* __restrict__ bias,
                            const float* __restrict__ phi)
{
    __shared__ float sw1[32], sw2[32];
    const int t = threadIdx.x;
    const int gid = blockIdx.x * 256 + t;
    if (t < 32) { sw1[t] = w1[t]; sw2[t] = w2[t]; }
    __syncthreads();

    if (gid <= GT) {
        float d = (float)gid * (64.0f / (float)GT);
        float z = b2[0], bb = b1[0];
        #pragma unroll
        for (int g = 0; g < 32; g++) {
            float s = 1.0f / (1.0f + __expf(-(d * sw1[g] + bb)));
            z += s * sw2[g];
        }
        g_gate_table[gid] = 1.0f / (1.0f + __expf(-z));
    }
    // fp16 W image: row n, chunk c (k16), quad q -> halves {k0,k0+1,k0+8,k0+9}
    if (gid < 4096) {
        int n = gid >> 5, c = (gid >> 2) & 7, q = gid & 3;
        int k0 = c * 16 + q * 2;
        __half2 h0 = __floats2half2_rn(W[k0 * DD + n],       W[(k0 + 1) * DD + n]);
        __half2 h1 = __floats2half2_rn(W[(k0 + 8) * DD + n], W[(k0 + 9) * DD + n]);
        *(__half2*)(g_Wh + n * 144 + c * 16 + q * 4)     = h0;
        *(__half2*)(g_Wh + n * 144 + c * 16 + q * 4 + 2) = h1;
    }
    if (gid < 1024) {
        int n = gid >> 3, j = gid & 7;
        *(uint32_t*)(g_Wh + n * 144 + 128 + j * 2) = 0;
    }
    // u, v, c0, c1 via coalesced warp reductions (block 0)
    if (blockIdx.x == 0) {
        const int w = t >> 5, l = t & 31;
        float pn0 = phi[l], pn1 = phi[l + 32], pn2 = phi[l + 64], pn3 = phi[l + 96];
        float ps0 = phi[DD + l], ps1 = phi[DD + l + 32];
        float ps2 = phi[DD + l + 64], ps3 = phi[DD + l + 96];
        #pragma unroll
        for (int rr = 0; rr < 16; rr++) {
            const int r = w * 16 + rr;
            float w0 = W[r * DD + l],      w1v = W[r * DD + l + 32];
            float w2v = W[r * DD + l + 64], w3 = W[r * DD + l + 96];
            float pu = w0 * pn0 + w1v * pn1 + w2v * pn2 + w3 * pn3;
            float pv = w0 * ps0 + w1v * ps1 + w2v * ps2 + w3 * ps3;
            #pragma unroll
            for (int off = 16; off; off >>= 1) {
                pu += __shfl_xor_sync(0xffffffffu, pu, off);
                pv += __shfl_xor_sync(0xffffffffu, pv, off);
            }
            if (l == 0) { g_u[r] = pu; g_v[r] = pv; }
        }
        if (w < 2) {
            float b0 = bias[l], b1v = bias[l + 32], b2v = bias[l + 64], b3 = bias[l + 96];
            float p = (w == 0)
                ? (b0 * pn0 + b1v * pn1 + b2v * pn2 + b3 * pn3)
                : (b0 * ps0 + b1v * ps1 + b2v * ps2 + b3 * ps3);
            #pragma unroll
            for (int off = 16; off; off >>= 1)
                p += __shfl_xor_sync(0xffffffffu, p, off);
            if (l == 0) { if (w == 0) g_c0 = p; else g_c1 = p; }
        }
    }
}

// ---------------- K2: streaming attention, register double buffering ---------
// NO cp.async anywhere in this kernel (toolchain-safe; see R8-R11 bisection).
__global__ void __launch_bounds__(256) stream_kernel(
    const float* __restrict__ x_self, const float* __restrict__ x_nb,
    const float* __restrict__ deg,
    const float* __restrict__ wsp, const float* __restrict__ wnp)
{
    extern __shared__ float smf[];
    const int t = threadIdx.x, lane = t & 31, wid = t >> 5;
    const int pair0 = blockIdx.x * PAIRS;

    // per-thread fixed load coordinates
    const int xrow[8] = { (t+0*256)>>5, (t+1*256)>>5, (t+2*256)>>5, (t+3*256)>>5,
                          (t+4*256)>>5, (t+5*256)>>5, (t+6*256)>>5, (t+7*256)>>5 };
    const int xc4 = t & 31;
    const int srow = t >> 7, scol = t & 127;

    // u/v into smem once (plain loads)
    if (t < 128) smf[U_O + t] = g_u[t];
    else         smf[V_O + (t - 128)] = g_v[t - 128];

    const float wsv = wsp[0], wnv = wnp[0];
    const float c0 = g_c0, c1 = g_c1;

    // ---- prologue: tile 0 into registers ----
    float4 rx[8];
    float rxs, rdg = 0.f;
    {
        const float4* Ab4 = (const float4*)(x_nb + (size_t)pair0 * 2 * KNB * DD);
        #pragma unroll
        for (int i = 0; i < 8; i++)
            rx[i] = Ab4[xrow[i] * 32 + xc4];
        rxs = x_self[(size_t)(pair0 * 2 + srow) * DD + scol];
        if (wid < 2) rdg = deg[(size_t)pair0 * 2 * KNB + wid * 32 + lane];
    }

    for (int it = 0; it < PAIRS; it++) {
        const int node0 = (pair0 + it) * 2;

        // ---- store current tile regs -> smem ----
        #pragma unroll
        for (int i = 0; i < 8; i++)
            *(float4*)(smf + X_O + xrow[i] * XSTR + xc4 * 4) = rx[i];
        smf[XS_O + srow * DD + scol] = rxs;
        const float dcur = rdg;
        __syncthreads();                    // tile `it` visible to all

        // ---- issue next tile's loads (results consumed next iteration) ----
        if (it + 1 < PAIRS) {
            const float4* Ab4 = (const float4*)(x_nb + (size_t)(node0 + 2) * KNB * DD);
            #pragma unroll
            for (int i = 0; i < 8; i++)
                rx[i] = Ab4[xrow[i] * 32 + xc4];
            rxs = x_self[(size_t)(node0 + 2 + srow) * DD + scol];
            if (wid < 2) rdg = deg[(size_t)(node0 + 2) * KNB + wid * 32 + lane];
        }

        // ---- raw scores: x_nb . u (warp w -> rows 8w..8w+7) ----
        {
            float uv0 = smf[U_O + lane], uv1 = smf[U_O + lane + 32];
            float uv2 = smf[U_O + lane + 64], uv3 = smf[U_O + lane + 96];
            #pragma unroll
            for (int i = 0; i < 8; i++) {
                const int row = wid * 8 + i;
                const float* Xr = smf + X_O + row * XSTR;
                float p = Xr[lane] * uv0 + Xr[lane + 32] * uv1
                        + Xr[lane + 64] * uv2 + Xr[lane + 96] * uv3;
                #pragma unroll
                for (int off = 16; off; off >>= 1)
                    p += __shfl_xor_sync(0xffffffffu, p, off);
                if (lane == 0) smf[SC_O + row] = p;
            }
        }
        // ---- s_self: x_self . v (warps 0,1) ----
        if (wid < 2) {
            const float* Xr = smf + XS_O + wid * DD;
            float p = Xr[lane] * smf[V_O + lane] + Xr[lane + 32] * smf[V_O + lane + 32]
                    + Xr[lane + 64] * smf[V_O + lane + 64] + Xr[lane + 96] * smf[V_O + lane + 96];
            #pragma unroll
            for (int off = 16; off; off >>= 1)
                p += __shfl_xor_sync(0xffffffffu, p, off);
            if (lane == 0) smf[SS_O + wid] = p;
        }
        __syncthreads();

        // ---- leaky + softmax + gate (warp per node) ----
        if (wid < 2) {
            float s = smf[SC_O + wid * 32 + lane] + c0 + smf[SS_O + wid] + c1;
            s = (s > 0.f) ? s : 0.2f * s;
            float m = s;
            #pragma unroll
            for (int off = 16; off; off >>= 1)
                m = fmaxf(m, __shfl_xor_sync(0xffffffffu, m, off));
            float e = __expf(s - m);
            float ss = e;
            #pragma unroll
            for (int off = 16; off; off >>= 1)
                ss += __shfl_xor_sync(0xffffffffu, ss, off);
            float u = fminf(fmaxf(dcur * ((float)GT / 64.0f), 0.0f), (float)GT - 0.001f);
            int ix = (int)u; float fr = u - (float)ix;
            float g0 = g_gate_table[ix];
            float gt = g0 + (g_gate_table[ix + 1] - g0) * fr;
            float a = (e / ss) * gt;
            smf[ATT_O + wid * 32 + lane] = a;
            float gs = a;
            #pragma unroll
            for (int off = 16; off; off >>= 1)
                gs += __shfl_xor_sync(0xffffffffu, gs, off);
            if (lane == 0) g_beta[node0 + wid] = wsv + wnv * gs;
        }
        __syncthreads();

        // ---- weighted neighbor sum + z write (128 threads per node) ----
        {
            const int node = t >> 7, c = t & 127;
            const float* Xn = smf + X_O + node * 32 * XSTR + c;
            const float* At = smf + ATT_O + node * 32;
            float y = 0.f;
            #pragma unroll
            for (int k = 0; k < 32; k++)
                y = fmaf(At[k], Xn[k * XSTR], y);
            float z = wsv * smf[XS_O + node * DD + c] + wnv * y;
            g_z[(size_t)(node0 + node) * DD + c] = z;
        }
        __syncthreads();    // smem reusable for next iteration's store
    }
}

// ---------------- K3: out = relu(z @ W + beta_n * b) -------------------------
__global__ void __launch_bounds__(256, 2) out_kernel(
    const float* __restrict__ bias, float* __restrict__ out)
{
    extern __shared__ char smc[];
    const uint32_t smem_base = s2u(smc);
    float* smf = (float*)(smc + EP_OFF_B);
    const int t = threadIdx.x, lane = t & 31, wid = t >> 5;
    const int wm = wid & 3, wn = wid >> 2, la = lane & 3, lr = lane >> 2;
    float* bias_s = smf;
    float* beta_s = smf + 128;

    const int row_base = blockIdx.x * 128;
    int valid = NN - row_base; if (valid > 128) valid = 128;

    if (t < 128) {
        bias_s[t] = bias[t];
        int gr = row_base + t;
        beta_s[t] = (gr < NN) ? g_beta[gr] : 0.f;
    }

    float acc[2][8][4] = {};
    gemm_pipe(smc, smem_base, g_z + (size_t)row_base * DD, valid, acc, wm, wn, lane);

    const int r = wm * 32 + lr;
    const float be0 = beta_s[r], be1 = beta_s[r + 8];
    const float be2 = beta_s[r + 16], be3 = beta_s[r + 24];
    #pragma unroll
    for (int nt = 0; nt < 8; nt++) {
        const int c = wn * 64 + nt * 8 + la * 2;
        const float b0 = bias_s[c], b1 = bias_s[c + 1];
        float o00 = acc[0][nt][0] + be0 * b0, o01 = acc[0][nt][1] + be0 * b1;
        float o10 = acc[0][nt][2] + be1 * b0, o11 = acc[0][nt][3] + be1 * b1;
        float o20 = acc[1][nt][0] + be2 * b0, o21 = acc[1][nt][1] + be2 * b1;
        float o30 = acc[1][nt][2] + be3 * b0, o31 = acc[1][nt][3] + be3 * b1;
        o00 = o00 > 0.f ? o00 : 0.f;  o01 = o01 > 0.f ? o01 : 0.f;
        o10 = o10 > 0.f ? o10 : 0.f;  o11 = o11 > 0.f ? o11 : 0.f;
        o20 = o20 > 0.f ? o20 : 0.f;  o21 = o21 > 0.f ? o21 : 0.f;
        o30 = o30 > 0.f ? o30 : 0.f;  o31 = o31 > 0.f ? o31 : 0.f;
        if (r      < valid) *(float2*)(out + (size_t)(row_base + r     ) * DD + c) = make_float2(o00, o01);
        if (r + 8  < valid) *(float2*)(out + (size_t)(row_base + r + 8 ) * DD + c) = make_float2(o10, o11);
        if (r + 16 < valid) *(float2*)(out + (size_t)(row_base + r + 16) * DD + c) = make_float2(o20, o21);
        if (r + 24 < valid) *(float2*)(out + (size_t)(row_base + r + 24) * DD + c) = make_float2(o30, o31);
    }
}

// ---------------- launch -----------------------------------------------------
extern "C" void kernel_launch(void* const* d_in, const int* in_sizes, int n_in,
                              void* d_out, int out_size)
{
    const float* x_self = (const float*)d_in[0];
    const float* x_nb   = (const float*)d_in[1];
    const float* deg    = (const float*)d_in[2];
    const float* W      = (const float*)d_in[3];
    const float* bias   = (const float*)d_in[4];
    const float* phi    = (const float*)d_in[5];
    const float* w1     = (const float*)d_in[6];
    const float* b1     = (const float*)d_in[7];
    const float* w2     = (const float*)d_in[8];
    const float* b2     = (const float*)d_in[9];
    const float* wsp    = (const float*)d_in[10];
    const float* wnp    = (const float*)d_in[11];
    float* out = (float*)d_out;

    cudaFuncSetAttribute(stream_kernel, cudaFuncAttributeMaxDynamicSharedMemorySize, K2_SMEM);
    cudaFuncSetAttribute(out_kernel, cudaFuncAttributeMaxDynamicSharedMemorySize, SMEM_TOTAL);

    init_kernel<<<17, 256>>>(w1, b1, w2, b2, W, bias, phi);
    stream_kernel<<<NN / (2 * PAIRS), 256, K2_SMEM>>>(x_self, x_nb, deg, wsp, wnp);
    out_kernel<<<(NN + 127) / 128, 256, SMEM_TOTAL>>>(bias, out);
}

// round 13
// speedup vs baseline: 3.9520x; 1.3375x over previous
#include <cuda_runtime.h>
#include <cuda_fp16.h>
#include <cstdint>

#define NN 20000
#define KNB 32
#define DD 128
#define GT 4096
#define PAIRS 4            // node-pairs per K2 CTA

// ---------------- device scratch (no runtime allocation) --------------------
__device__ float g_gate_table[GT + 1];
__device__ __align__(16) __half g_Wh[128 * 144];  // fp16 W image, [n][k-interleaved], 288B rows
__device__ __align__(16) float g_u[DD];           // W @ phi_n
__device__ __align__(16) float g_v[DD];           // W @ phi_s
__device__ float g_c0, g_c1;                      // b.phi_n, b.phi_s
__device__ __align__(16) float g_z[NN * DD];      // ws*x_self + wn*y
__device__ float g_beta[NN];                      // ws + wn*gs

// ---------------- K3 smem layout (bytes) — same as R6/R7/R10 GEMM -----------
#define A_STRIDE_F 40
#define A_BUF_B   20480
#define W_OFF_B   40960
#define EP_OFF_B  77824
#define SMEM_TOTAL 83008

// ---------------- K2 static smem (float offsets) -----------------------------
#define PN_O   0            // 8 warps x 2 nodes x 32 lanes x float4 = 2048
#define SC_O   2048         // 64 raw scores
#define SSP_O  2112         // 8 per-warp s_self partials
#define ATT_O  2120         // 64 att*gate
#define K2_FLOATS 2184

// ---------------- helpers ----------------------------------------------------
__device__ __forceinline__ uint32_t s2u(const void* p) {
    return (uint32_t)__cvta_generic_to_shared(p);
}
__device__ __forceinline__ void cp16p(uint32_t sa, const float* g, bool v) {
    int sz = v ? 16 : 0;
    asm volatile("cp.async.cg.shared.global [%0], [%1], 16, %2;" :: "r"(sa), "l"(g), "r"(sz));
}
#define CP_COMMIT() asm volatile("cp.async.commit_group;" ::: "memory")
#define CP_WAIT1()  asm volatile("cp.async.wait_group 1;" ::: "memory")
#define CP_WAIT0()  asm volatile("cp.async.wait_group 0;" ::: "memory")

__device__ __forceinline__ void mma16(float* c, const uint32_t* a, uint32_t b0, uint32_t b1) {
    asm volatile(
        "mma.sync.aligned.m16n8k16.row.col.f32.f16.f16.f32 "
        "{%0,%1,%2,%3}, {%4,%5,%6,%7}, {%8,%9}, {%0,%1,%2,%3};\n"
        : "+f"(c[0]), "+f"(c[1]), "+f"(c[2]), "+f"(c[3])
        : "r"(a[0]), "r"(a[1]), "r"(a[2]), "r"(a[3]), "r"(b0), "r"(b1));
}
__device__ __forceinline__ uint32_t pack2(float lo, float hi) {
    __half2 h = __floats2half2_rn(lo, hi);
    return *(uint32_t*)&h;
}

// ---------------- K3 GEMM machinery (proven R6-R12) --------------------------
__device__ __forceinline__ void stageA(uint32_t smem_base, int buf,
                                       const float* __restrict__ Ag, int valid) {
    const int t = threadIdx.x;
    const uint32_t base = smem_base + buf * A_BUF_B;
    #pragma unroll
    for (int i = 0; i < 4; i++) {
        int e = t + i * 256;
        int row = e >> 3, c4 = (e & 7) << 2;
        cp16p(base + row * 160 + c4 * 4, Ag + row * DD + c4, row < valid);
    }
}

__device__ __forceinline__ void compute_chunk(
    const float* __restrict__ As, const char* __restrict__ Wb, int kc,
    float (&acc)[2][8][4], int wm, int wn, int lane)
{
    const int q2 = (lane & 3) * 2;
    const int lr = lane >> 2;
    const int r0 = wm * 32 + lr;
    #pragma unroll
    for (int s = 0; s < 2; s++) {
        const int kk = s * 16;
        float2 A00 = *(const float2*)(As + (r0     ) * A_STRIDE_F + kk + q2);
        float2 A01 = *(const float2*)(As + (r0 +  8) * A_STRIDE_F + kk + q2);
        float2 A02 = *(const float2*)(As + (r0     ) * A_STRIDE_F + kk + q2 + 8);
        float2 A03 = *(const float2*)(As + (r0 +  8) * A_STRIDE_F + kk + q2 + 8);
        float2 A10 = *(const float2*)(As + (r0 + 16) * A_STRIDE_F + kk + q2);
        float2 A11 = *(const float2*)(As + (r0 + 24) * A_STRIDE_F + kk + q2);
        float2 A12 = *(const float2*)(As + (r0 + 16) * A_STRIDE_F + kk + q2 + 8);
        float2 A13 = *(const float2*)(As + (r0 + 24) * A_STRIDE_F + kk + q2 + 8);
        uint32_t a0[4], a1[4];
        a0[0] = pack2(A00.x, A00.y); a0[1] = pack2(A01.x, A01.y);
        a0[2] = pack2(A02.x, A02.y); a0[3] = pack2(A03.x, A03.y);
        a1[0] = pack2(A10.x, A10.y); a1[1] = pack2(A11.x, A11.y);
        a1[2] = pack2(A12.x, A12.y); a1[3] = pack2(A13.x, A13.y);
        const int coff = (kc * 2 + s) * 32 + q2 * 4;
        #pragma unroll
        for (int nt = 0; nt < 8; nt++) {
            const int n = wn * 64 + nt * 8 + lr;
            uint2 b = *(const uint2*)(Wb + n * 288 + coff);
            mma16(acc[0][nt], a0, b.x, b.y);
            mma16(acc[1][nt], a1, b.x, b.y);
        }
    }
}

__device__ __forceinline__ void gemm_pipe(
    char* smc, uint32_t smem_base, const float* __restrict__ Abase, int valid,
    float (&acc)[2][8][4], int wm, int wn, int lane)
{
    const int t = threadIdx.x;
    #pragma unroll
    for (int i = 0; i < 9; i++) {
        int e = t + i * 256;
        cp16p(smem_base + W_OFF_B + e * 16,
              (const float*)((const char*)g_Wh + e * 16), true);
    }
    stageA(smem_base, 0, Abase, valid);
    CP_COMMIT();

    const char* Wb = smc + W_OFF_B;
    #pragma unroll
    for (int kc = 0; kc < 4; kc++) {
        if (kc < 3) {
            stageA(smem_base, (kc + 1) & 1, Abase + (kc + 1) * 32, valid);
            CP_COMMIT();
            CP_WAIT1();
        } else {
            CP_WAIT0();
        }
        __syncthreads();
        compute_chunk((const float*)(smc + (kc & 1) * A_BUF_B), Wb, kc,
                      acc, wm, wn, lane);
        __syncthreads();
    }
}

// ---------------- K1: init — warp-per-table-entry, spread across SMs ---------
// grid 530: blocks 0..512 gate table (8 entries/block, lane=g), 513..528 W image,
// 529 u/v/c0/c1.
__global__ void __launch_bounds__(256) init_kernel(
    const float* __restrict__ w1, const float* __restrict__ b1,
    const float* __restrict__ w2, const float* __restrict__ b2,
    const float* __restrict__ W, const float* __restrict__ bias,
    const float* __restrict__ phi)
{
    const int t = threadIdx.x, lane = t & 31, w = t >> 5;
    const int bx = blockIdx.x;

    if (bx <= 512) {
        // gate table: one warp per entry
        const int gw = bx * 8 + w;
        if (gw <= GT) {
            float d = (float)gw * (64.0f / (float)GT);
            float s = 1.0f / (1.0f + __expf(-(d * w1[lane] + b1[0])));
            float p = s * w2[lane];
            #pragma unroll
            for (int off = 16; off; off >>= 1)
                p += __shfl_xor_sync(0xffffffffu, p, off);
            if (lane == 0)
                g_gate_table[gw] = 1.0f / (1.0f + __expf(-(p + b2[0])));
        }
    } else if (bx <= 528) {
        // fp16 W image: row n, chunk c (k16), quad q -> halves {k0,k0+1,k0+8,k0+9}
        const int gid2 = (bx - 513) * 256 + t;
        {
            int n = gid2 >> 5, c = (gid2 >> 2) & 7, q = gid2 & 3;
            int k0 = c * 16 + q * 2;
            __half2 h0 = __floats2half2_rn(W[k0 * DD + n],       W[(k0 + 1) * DD + n]);
            __half2 h1 = __floats2half2_rn(W[(k0 + 8) * DD + n], W[(k0 + 9) * DD + n]);
            *(__half2*)(g_Wh + n * 144 + c * 16 + q * 4)     = h0;
            *(__half2*)(g_Wh + n * 144 + c * 16 + q * 4 + 2) = h1;
        }
        if (gid2 < 1024) {
            int n = gid2 >> 3, j = gid2 & 7;
            *(uint32_t*)(g_Wh + n * 144 + 128 + j * 2) = 0;
        }
    } else {
        // u, v, c0, c1 via coalesced warp reductions
        float pn0 = phi[lane], pn1 = phi[lane + 32], pn2 = phi[lane + 64], pn3 = phi[lane + 96];
        float ps0 = phi[DD + lane], ps1 = phi[DD + lane + 32];
        float ps2 = phi[DD + lane + 64], ps3 = phi[DD + lane + 96];
        #pragma unroll
        for (int rr = 0; rr < 16; rr++) {
            const int r = w * 16 + rr;
            float w0 = W[r * DD + lane],      w1v = W[r * DD + lane + 32];
            float w2v = W[r * DD + lane + 64], w3 = W[r * DD + lane + 96];
            float pu = w0 * pn0 + w1v * pn1 + w2v * pn2 + w3 * pn3;
            float pv = w0 * ps0 + w1v * ps1 + w2v * ps2 + w3 * ps3;
            #pragma unroll
            for (int off = 16; off; off >>= 1) {
                pu += __shfl_xor_sync(0xffffffffu, pu, off);
                pv += __shfl_xor_sync(0xffffffffu, pv, off);
            }
            if (lane == 0) { g_u[r] = pu; g_v[r] = pv; }
        }
        if (w < 2) {
            float b0 = bias[lane], b1v = bias[lane + 32];
            float b2v = bias[lane + 64], b3 = bias[lane + 96];
            float p = (w == 0)
                ? (b0 * pn0 + b1v * pn1 + b2v * pn2 + b3 * pn3)
                : (b0 * ps0 + b1v * ps1 + b2v * ps2 + b3 * ps3);
            #pragma unroll
            for (int off = 16; off; off >>= 1)
                p += __shfl_xor_sync(0xffffffffu, p, off);
            if (lane == 0) { if (w == 0) g_c0 = p; else g_c1 = p; }
        }
    }
}

// ---------------- K2: register-direct streaming attention --------------------
// X tile never touches smem: warp w fragment i = full row (w+8i), lanes = col quads.
// NO cp.async (toolchain constraint from R8-R11 bisection).
__global__ void __launch_bounds__(256) stream_kernel(
    const float* __restrict__ x_self, const float* __restrict__ x_nb,
    const float* __restrict__ deg,
    const float* __restrict__ wsp, const float* __restrict__ wnp)
{
    __shared__ float smf[K2_FLOATS];
    const int t = threadIdx.x, lane = t & 31, w = t >> 5;
    const int pair0 = blockIdx.x * PAIRS;
    const int node_t = t >> 7, col_t = t & 127;

    const float4 u4 = *(const float4*)(g_u + lane * 4);
    const float vv = g_v[col_t];
    const float wsv = wsp[0], wnv = wnp[0];
    const float c0 = g_c0, c1 = g_c1;

    float4 rx[2][8];
    float rxs[2], rdg[2];

    // prologue: tile 0 -> buffer 0
    {
        const float4* Ab4 = (const float4*)(x_nb + (size_t)pair0 * 2 * KNB * DD);
        #pragma unroll
        for (int i = 0; i < 8; i++)
            rx[0][i] = Ab4[(w + 8 * i) * 32 + lane];
        rxs[0] = x_self[(size_t)(pair0 * 2 + node_t) * DD + col_t];
        rdg[0] = (w < 2) ? deg[(size_t)pair0 * 2 * KNB + w * 32 + lane] : 0.f;
    }

    #pragma unroll
    for (int it = 0; it < PAIRS; it++) {
        const int cb = it & 1, nb = cb ^ 1;
        const int node0 = (pair0 + it) * 2;

        // prefetch next tile into the other register buffer
        if (it + 1 < PAIRS) {
            const float4* Ab4 = (const float4*)(x_nb + (size_t)(node0 + 2) * KNB * DD);
            #pragma unroll
            for (int i = 0; i < 8; i++)
                rx[nb][i] = Ab4[(w + 8 * i) * 32 + lane];
            rxs[nb] = x_self[(size_t)(node0 + 2 + node_t) * DD + col_t];
            rdg[nb] = (w < 2) ? deg[(size_t)(node0 + 2) * KNB + w * 32 + lane] : 0.f;
        }

        // ---- score partials from registers: v[i] = row(w+8i) . u (this lane's quad)
        float v[8];
        #pragma unroll
        for (int i = 0; i < 8; i++) {
            float4 x = rx[cb][i];
            v[i] = x.x * u4.x + x.y * u4.y + x.z * u4.z + x.w * u4.w;
        }
        // packed 8-value butterfly: 9 shfl; lane ends with row w + 8*(lane>>2)
        #pragma unroll
        for (int j = 0; j < 4; j++) {
            float give = (lane & 16) ? v[j] : v[j + 4];
            float keep = (lane & 16) ? v[j + 4] : v[j];
            v[j] = keep + __shfl_xor_sync(0xffffffffu, give, 16);
        }
        #pragma unroll
        for (int j = 0; j < 2; j++) {
            float give = (lane & 8) ? v[j] : v[j + 2];
            float keep = (lane & 8) ? v[j + 2] : v[j];
            v[j] = keep + __shfl_xor_sync(0xffffffffu, give, 8);
        }
        {
            float give = (lane & 4) ? v[0] : v[1];
            float keep = (lane & 4) ? v[1] : v[0];
            v[0] = keep + __shfl_xor_sync(0xffffffffu, give, 4);
        }
        v[0] += __shfl_xor_sync(0xffffffffu, v[0], 2);
        v[0] += __shfl_xor_sync(0xffffffffu, v[0], 1);
        if ((lane & 3) == 0) smf[SC_O + w + 8 * (lane >> 2)] = v[0];

        // ---- s_self partial: rxs . v (per-warp reduce, 8 partials)
        {
            float p = rxs[cb] * vv;
            #pragma unroll
            for (int off = 16; off; off >>= 1)
                p += __shfl_xor_sync(0xffffffffu, p, off);
            if (lane == 0) smf[SSP_O + w] = p;
        }
        __syncthreads();

        // ---- leaky + softmax + gate (warp per node) ----
        if (w < 2) {
            float ssl = smf[SSP_O + w * 4] + smf[SSP_O + w * 4 + 1]
                      + smf[SSP_O + w * 4 + 2] + smf[SSP_O + w * 4 + 3];
            float s = smf[SC_O + w * 32 + lane] + c0 + ssl + c1;
            s = (s > 0.f) ? s : 0.2f * s;
            float m = s;
            #pragma unroll
            for (int off = 16; off; off >>= 1)
                m = fmaxf(m, __shfl_xor_sync(0xffffffffu, m, off));
            float e = __expf(s - m);
            float ss = e;
            #pragma unroll
            for (int off = 16; off; off >>= 1)
                ss += __shfl_xor_sync(0xffffffffu, ss, off);
            float u = fminf(fmaxf(rdg[cb] * ((float)GT / 64.0f), 0.0f), (float)GT - 0.001f);
            int ix = (int)u; float fr = u - (float)ix;
            float g0 = g_gate_table[ix];
            float gt = g0 + (g_gate_table[ix + 1] - g0) * fr;
            float a = (e / ss) * gt;
            smf[ATT_O + w * 32 + lane] = a;
            float gs = a;
            #pragma unroll
            for (int off = 16; off; off >>= 1)
                gs += __shfl_xor_sync(0xffffffffu, gs, off);
            if (lane == 0) g_beta[node0 + w] = wsv + wnv * gs;
        }
        __syncthreads();

        // ---- weighted-sum partials from registers (att via broadcast LDS) ----
        {
            float4 pn0 = make_float4(0.f, 0.f, 0.f, 0.f);
            float4 pn1 = make_float4(0.f, 0.f, 0.f, 0.f);
            #pragma unroll
            for (int i = 0; i < 4; i++) {
                float a = smf[ATT_O + w + 8 * i];
                float4 x = rx[cb][i];
                pn0.x += a * x.x; pn0.y += a * x.y; pn0.z += a * x.z; pn0.w += a * x.w;
            }
            #pragma unroll
            for (int i = 4; i < 8; i++) {
                float a = smf[ATT_O + w + 8 * i];
                float4 x = rx[cb][i];
                pn1.x += a * x.x; pn1.y += a * x.y; pn1.z += a * x.z; pn1.w += a * x.w;
            }
            *(float4*)(smf + PN_O + (w * 64 + lane) * 4)      = pn0;
            *(float4*)(smf + PN_O + (w * 64 + 32 + lane) * 4) = pn1;
        }
        __syncthreads();

        // ---- final: sum 8 warp-partials, write z ----
        {
            float y = 0.f;
            #pragma unroll
            for (int ww = 0; ww < 8; ww++)
                y += smf[PN_O + ww * 256 + node_t * 128 + col_t];
            float z = wsv * rxs[cb] + wnv * y;
            g_z[(size_t)(node0 + node_t) * DD + col_t] = z;
        }
        // no trailing sync needed: PN next written only after next sync#2,
        // SC/SSP next written before next sync#1 but last read before this sync#2.
    }
}

// ---------------- K3: out = relu(z @ W + beta_n * b) -------------------------
__global__ void __launch_bounds__(256, 2) out_kernel(
    const float* __restrict__ bias, float* __restrict__ out)
{
    extern __shared__ char smc[];
    const uint32_t smem_base = s2u(smc);
    float* smf = (float*)(smc + EP_OFF_B);
    const int t = threadIdx.x, lane = t & 31, wid = t >> 5;
    const int wm = wid & 3, wn = wid >> 2, la = lane & 3, lr = lane >> 2;
    float* bias_s = smf;
    float* beta_s = smf + 128;

    const int row_base = blockIdx.x * 128;
    int valid = NN - row_base; if (valid > 128) valid = 128;

    if (t < 128) {
        bias_s[t] = bias[t];
        int gr = row_base + t;
        beta_s[t] = (gr < NN) ? g_beta[gr] : 0.f;
    }

    float acc[2][8][4] = {};
    gemm_pipe(smc, smem_base, g_z + (size_t)row_base * DD, valid, acc, wm, wn, lane);

    const int r = wm * 32 + lr;
    const float be0 = beta_s[r], be1 = beta_s[r + 8];
    const float be2 = beta_s[r + 16], be3 = beta_s[r + 24];
    #pragma unroll
    for (int nt = 0; nt < 8; nt++) {
        const int c = wn * 64 + nt * 8 + la * 2;
        const float b0 = bias_s[c], b1 = bias_s[c + 1];
        float o00 = acc[0][nt][0] + be0 * b0, o01 = acc[0][nt][1] + be0 * b1;
        float o10 = acc[0][nt][2] + be1 * b0, o11 = acc[0][nt][3] + be1 * b1;
        float o20 = acc[1][nt][0] + be2 * b0, o21 = acc[1][nt][1] + be2 * b1;
        float o30 = acc[1][nt][2] + be3 * b0, o31 = acc[1][nt][3] + be3 * b1;
        o00 = o00 > 0.f ? o00 : 0.f;  o01 = o01 > 0.f ? o01 : 0.f;
        o10 = o10 > 0.f ? o10 : 0.f;  o11 = o11 > 0.f ? o11 : 0.f;
        o20 = o20 > 0.f ? o20 : 0.f;  o21 = o21 > 0.f ? o21 : 0.f;
        o30 = o30 > 0.f ? o30 : 0.f;  o31 = o31 > 0.f ? o31 : 0.f;
        if (r      < valid) *(float2*)(out + (size_t)(row_base + r     ) * DD + c) = make_float2(o00, o01);
        if (r + 8  < valid) *(float2*)(out + (size_t)(row_base + r + 8 ) * DD + c) = make_float2(o10, o11);
        if (r + 16 < valid) *(float2*)(out + (size_t)(row_base + r + 16) * DD + c) = make_float2(o20, o21);
        if (r + 24 < valid) *(float2*)(out + (size_t)(row_base + r + 24) * DD + c) = make_float2(o30, o31);
    }
}

// ---------------- launch -----------------------------------------------------
extern "C" void kernel_launch(void* const* d_in, const int* in_sizes, int n_in,
                              void* d_out, int out_size)
{
    const float* x_self = (const float*)d_in[0];
    const float* x_nb   = (const float*)d_in[1];
    const float* deg    = (const float*)d_in[2];
    const float* W      = (const float*)d_in[3];
    const float* bias   = (const float*)d_in[4];
    const float* phi    = (const float*)d_in[5];
    const float* w1     = (const float*)d_in[6];
    const float* b1     = (const float*)d_in[7];
    const float* w2     = (const float*)d_in[8];
    const float* b2     = (const float*)d_in[9];
    const float* wsp    = (const float*)d_in[10];
    const float* wnp    = (const float*)d_in[11];
    float* out = (float*)d_out;

    cudaFuncSetAttribute(out_kernel, cudaFuncAttributeMaxDynamicSharedMemorySize, SMEM_TOTAL);

    init_kernel<<<530, 256>>>(w1, b1, w2, b2, W, bias, phi);
    stream_kernel<<<NN / (2 * PAIRS), 256>>>(x_self, x_nb, deg, wsp, wnp);
    out_kernel<<<(NN + 127) / 128, 256, SMEM_TOTAL>>>(bias, out);
}